// round 5
// baseline (speedup 1.0000x reference)
#include <cuda_runtime.h>
#include <cstdint>

// ---------------- problem constants ----------------
#define B_    2
#define S_    2048
#define HID_  4096
#define NH_   32
#define NKV_  8
#define HD_   128
#define G_    128
#define M_    (B_*S_)        // 4096 tokens
#define QDIM  (NH_*HD_)      // 4096
#define KVDIM (NKV_*HD_)     // 1024

// ---------------- device scratch (no allocations allowed) ----------------
__device__ float g_Wq[QDIM*HID_];
__device__ float g_Wk[KVDIM*HID_];
__device__ float g_Wv[KVDIM*HID_];
__device__ float g_Wo[HID_*QDIM];
__device__ float g_Q [M_*QDIM];
__device__ float g_K [M_*KVDIM];
__device__ float g_V [M_*KVDIM];
__device__ float g_CTX[M_*QDIM];

// ---------------- dequant: w = (qw - 8) * scale[o][i/128] ----------------
__global__ void dequant_kernel(const int* __restrict__ qw,
                               const float* __restrict__ scale,
                               float* __restrict__ w,
                               int in_dim, int total4) {
    int idx = blockIdx.x * blockDim.x + threadIdx.x;
    if (idx >= total4) return;
    int i4 = idx << 2;
    int o  = i4 / in_dim;
    int i  = i4 - o * in_dim;
    float s = scale[o * (in_dim / G_) + (i >> 7)];
    int4 q = ((const int4*)qw)[idx];
    float4 r;
    r.x = (float)(q.x - 8) * s;
    r.y = (float)(q.y - 8) * s;
    r.z = (float)(q.z - 8) * s;
    r.w = (float)(q.w - 8) * s;
    ((float4*)w)[idx] = r;
}

// ---------------- GEMM: C[M,N] = A[M,K] * B[N,K]^T (both row-major) ------
// 128x128 tile, BK=32, 256 threads, 8x8 microtile.
__global__ __launch_bounds__(256) void gemm_nt_kernel(
    const float* __restrict__ A, const float* __restrict__ Bw,
    float* __restrict__ C, int M, int N, int K) {
    __shared__ float As[32][132];   // [k][m], padded
    __shared__ float Bs[32][132];   // [k][n], padded

    const int tid = threadIdx.x;
    const int tx = tid & 15, ty = tid >> 4;
    const int m0 = blockIdx.y << 7, n0 = blockIdx.x << 7;

    const int lrow = tid >> 3;        // 0..31
    const int lk   = (tid & 7) << 2;  // 0..28 step 4
    const float* Aptr = A + (size_t)(m0 + lrow) * K + lk;
    const float* Bptr = Bw + (size_t)(n0 + lrow) * K + lk;

    float acc[8][8];
#pragma unroll
    for (int i = 0; i < 8; ++i)
#pragma unroll
        for (int j = 0; j < 8; ++j) acc[i][j] = 0.f;

    for (int kk = 0; kk < K; kk += 32) {
#pragma unroll
        for (int it = 0; it < 4; ++it) {
            int row = lrow + it * 32;
            float4 a = *(const float4*)(Aptr + (size_t)(it * 32) * K + kk);
            As[lk + 0][row] = a.x; As[lk + 1][row] = a.y;
            As[lk + 2][row] = a.z; As[lk + 3][row] = a.w;
            float4 b = *(const float4*)(Bptr + (size_t)(it * 32) * K + kk);
            Bs[lk + 0][row] = b.x; Bs[lk + 1][row] = b.y;
            Bs[lk + 2][row] = b.z; Bs[lk + 3][row] = b.w;
        }
        __syncthreads();
#pragma unroll
        for (int k = 0; k < 32; ++k) {
            float4 a0 = *(const float4*)&As[k][ty * 8];
            float4 a1 = *(const float4*)&As[k][ty * 8 + 4];
            float4 b0 = *(const float4*)&Bs[k][tx * 8];
            float4 b1 = *(const float4*)&Bs[k][tx * 8 + 4];
            float ra[8] = {a0.x, a0.y, a0.z, a0.w, a1.x, a1.y, a1.z, a1.w};
            float rb[8] = {b0.x, b0.y, b0.z, b0.w, b1.x, b1.y, b1.z, b1.w};
#pragma unroll
            for (int i = 0; i < 8; ++i)
#pragma unroll
                for (int j = 0; j < 8; ++j)
                    acc[i][j] = fmaf(ra[i], rb[j], acc[i][j]);
        }
        __syncthreads();
    }

#pragma unroll
    for (int i = 0; i < 8; ++i) {
        float* crow = C + (size_t)(m0 + ty * 8 + i) * N + n0 + tx * 8;
        float4 c0 = {acc[i][0], acc[i][1], acc[i][2], acc[i][3]};
        float4 c1 = {acc[i][4], acc[i][5], acc[i][6], acc[i][7]};
        *(float4*)crow       = c0;
        *(float4*)(crow + 4) = c1;
    }
}

// ---------------- RoPE in place on Q and K -------------------------------
__global__ void rope_kernel(float* __restrict__ Q, float* __restrict__ K,
                            const float* __restrict__ cosp,
                            const float* __restrict__ sinp) {
    int t = blockIdx.x * blockDim.x + threadIdx.x;
    const int TOT = M_ * (NH_ + NKV_) * 64;
    if (t >= TOT) return;
    int d = t & 63;
    int r = t >> 6;
    int h = r % (NH_ + NKV_);
    int m = r / (NH_ + NKV_);
    float c1 = cosp[m * HD_ + d],      s1 = sinp[m * HD_ + d];
    float c2 = cosp[m * HD_ + d + 64], s2 = sinp[m * HD_ + d + 64];
    float* base = (h < NH_)
        ? (Q + (size_t)m * QDIM  + h * HD_)
        : (K + (size_t)m * KVDIM + (h - NH_) * HD_);
    float x1 = base[d], x2 = base[d + 64];
    base[d]      = x1 * c1 - x2 * s1;
    base[d + 64] = x2 * c2 + x1 * s2;
}

// ---------------- flash attention (fp32, causal) -------------------------
// grid (S/64, NH, B), 256 threads, 64q x 64k tiles, HD=128.
#define SKS 65   // padded stride for transposed Q/K and P tiles
#define ATTN_SMEM_FLOATS (128*SKS + 128*SKS + 64*128 + 64*SKS)

__global__ __launch_bounds__(256) void attn_kernel(
    const float* __restrict__ Q, const float* __restrict__ K,
    const float* __restrict__ V, float* __restrict__ CTX) {
    extern __shared__ float sm[];
    float* Qs = sm;                 // [128 d][65] transposed
    float* Ks = Qs + 128 * SKS;     // [128 d][65] transposed
    float* Vs = Ks + 128 * SKS;     // [64 c][128 d] natural
    float* Ps = Vs + 64 * 128;      // [64 r][65]

    const float SCALING = 0.08838834764831843f;   // 1/sqrt(128)
    const int qi = blockIdx.x, h = blockIdx.y, b = blockIdx.z;
    const int kvh = h >> 2;                        // NH/NKV = 4
    const int tid = threadIdx.x;
    const int tx = tid & 15, ty = tid >> 4;
    const int q0 = qi << 6;
    const int lrow = tid >> 5;                     // 0..7
    const int ld0  = (tid & 31) << 2;              // 0..124

    // load Q tile transposed: Qs[d][q]
    {
        const float* qb = Q + ((size_t)(b * S_ + q0)) * QDIM + h * HD_;
#pragma unroll
        for (int it = 0; it < 8; ++it) {
            int qr = it * 8 + lrow;
            float4 qv = *(const float4*)(qb + (size_t)qr * QDIM + ld0);
            Qs[(ld0 + 0) * SKS + qr] = qv.x;
            Qs[(ld0 + 1) * SKS + qr] = qv.y;
            Qs[(ld0 + 2) * SKS + qr] = qv.z;
            Qs[(ld0 + 3) * SKS + qr] = qv.w;
        }
    }

    float mrow[4], lsum[4], o[4][8];
#pragma unroll
    for (int i = 0; i < 4; ++i) {
        mrow[i] = -1e30f; lsum[i] = 0.f;
#pragma unroll
        for (int jj = 0; jj < 8; ++jj) o[i][jj] = 0.f;
    }

    const float* kb = K + ((size_t)(b * S_)) * KVDIM + kvh * HD_;
    const float* vb = V + ((size_t)(b * S_)) * KVDIM + kvh * HD_;

    for (int kt = 0; kt <= qi; ++kt) {
        const int k0 = kt << 6;
        __syncthreads();   // previous PV done before K/V overwrite
        // load K (transposed) and V (natural) tiles
#pragma unroll
        for (int it = 0; it < 8; ++it) {
            int kr = it * 8 + lrow;
            float4 kv4 = *(const float4*)(kb + (size_t)(k0 + kr) * KVDIM + ld0);
            Ks[(ld0 + 0) * SKS + kr] = kv4.x;
            Ks[(ld0 + 1) * SKS + kr] = kv4.y;
            Ks[(ld0 + 2) * SKS + kr] = kv4.z;
            Ks[(ld0 + 3) * SKS + kr] = kv4.w;
            float4 vv4 = *(const float4*)(vb + (size_t)(k0 + kr) * KVDIM + ld0);
            *(float4*)&Vs[kr * 128 + ld0] = vv4;
        }
        __syncthreads();

        // scores S[4][4]
        float sc[4][4];
#pragma unroll
        for (int i = 0; i < 4; ++i)
#pragma unroll
            for (int j = 0; j < 4; ++j) sc[i][j] = 0.f;
        for (int d = 0; d < 128; ++d) {
            float qv[4], kr4[4];
#pragma unroll
            for (int i = 0; i < 4; ++i) qv[i]  = Qs[d * SKS + ty * 4 + i];
#pragma unroll
            for (int j = 0; j < 4; ++j) kr4[j] = Ks[d * SKS + tx * 4 + j];
#pragma unroll
            for (int i = 0; i < 4; ++i)
#pragma unroll
                for (int j = 0; j < 4; ++j)
                    sc[i][j] = fmaf(qv[i], kr4[j], sc[i][j]);
        }

        const bool diag = (kt == qi);
#pragma unroll
        for (int i = 0; i < 4; ++i)
#pragma unroll
            for (int j = 0; j < 4; ++j) {
                float s = sc[i][j] * SCALING;
                if (diag && (k0 + tx * 4 + j) > (q0 + ty * 4 + i)) s = -1e30f;
                sc[i][j] = s;
            }

        // online softmax (row stats across the 16 tx lanes of each half-warp)
#pragma unroll
        for (int i = 0; i < 4; ++i) {
            float mn = fmaxf(fmaxf(sc[i][0], sc[i][1]), fmaxf(sc[i][2], sc[i][3]));
#pragma unroll
            for (int off = 8; off > 0; off >>= 1)
                mn = fmaxf(mn, __shfl_xor_sync(0xffffffffu, mn, off, 16));
            mn = fmaxf(mn, mrow[i]);
            float corr = __expf(mrow[i] - mn);
            mrow[i] = mn;
            float rs = 0.f;
#pragma unroll
            for (int j = 0; j < 4; ++j) {
                float p = __expf(sc[i][j] - mn);
                sc[i][j] = p;
                rs += p;
            }
#pragma unroll
            for (int off = 8; off > 0; off >>= 1)
                rs += __shfl_xor_sync(0xffffffffu, rs, off, 16);
            lsum[i] = lsum[i] * corr + rs;
#pragma unroll
            for (int jj = 0; jj < 8; ++jj) o[i][jj] *= corr;
        }

        // stage P
#pragma unroll
        for (int i = 0; i < 4; ++i)
#pragma unroll
            for (int j = 0; j < 4; ++j)
                Ps[(ty * 4 + i) * SKS + tx * 4 + j] = sc[i][j];
        __syncthreads();

        // O += P @ V
#pragma unroll 2
        for (int c = 0; c < 64; ++c) {
            float p0 = Ps[(ty * 4 + 0) * SKS + c];
            float p1 = Ps[(ty * 4 + 1) * SKS + c];
            float p2 = Ps[(ty * 4 + 2) * SKS + c];
            float p3 = Ps[(ty * 4 + 3) * SKS + c];
            float4 v0 = *(const float4*)&Vs[c * 128 + tx * 8];
            float4 v1 = *(const float4*)&Vs[c * 128 + tx * 8 + 4];
            float vr[8] = {v0.x, v0.y, v0.z, v0.w, v1.x, v1.y, v1.z, v1.w};
            float pr[4] = {p0, p1, p2, p3};
#pragma unroll
            for (int i = 0; i < 4; ++i)
#pragma unroll
                for (int jj = 0; jj < 8; ++jj)
                    o[i][jj] = fmaf(pr[i], vr[jj], o[i][jj]);
        }
    }

    // epilogue: normalize, write ctx in [b, s, h*HD+d] layout
#pragma unroll
    for (int i = 0; i < 4; ++i) {
        int q = q0 + ty * 4 + i;
        float iv = 1.0f / lsum[i];
        float* outp = CTX + ((size_t)(b * S_ + q)) * QDIM + h * HD_ + tx * 8;
        float4 r0 = {o[i][0] * iv, o[i][1] * iv, o[i][2] * iv, o[i][3] * iv};
        float4 r1 = {o[i][4] * iv, o[i][5] * iv, o[i][6] * iv, o[i][7] * iv};
        *(float4*)outp       = r0;
        *(float4*)(outp + 4) = r1;
    }
}

// ---------------- launch --------------------------------------------------
extern "C" void kernel_launch(void* const* d_in, const int* in_sizes, int n_in,
                              void* d_out, int out_size) {
    const float* hidden  = (const float*)d_in[0];
    const float* cosp    = (const float*)d_in[1];
    const float* sinp    = (const float*)d_in[2];
    // d_in[3] attention_mask: pure causal by construction -> applied analytically
    const int*   q_qw    = (const int*)  d_in[4];
    const float* q_scale = (const float*)d_in[5];
    const int*   k_qw    = (const int*)  d_in[6];
    const float* k_scale = (const float*)d_in[7];
    const int*   v_qw    = (const int*)  d_in[8];
    const float* v_scale = (const float*)d_in[9];
    const int*   o_qw    = (const int*)  d_in[10];
    const float* o_scale = (const float*)d_in[11];
    float* out = (float*)d_out;

    void* p;
    cudaGetSymbolAddress(&p, g_Wq);  float* Wq  = (float*)p;
    cudaGetSymbolAddress(&p, g_Wk);  float* Wk  = (float*)p;
    cudaGetSymbolAddress(&p, g_Wv);  float* Wv  = (float*)p;
    cudaGetSymbolAddress(&p, g_Wo);  float* Wo  = (float*)p;
    cudaGetSymbolAddress(&p, g_Q);   float* Qb  = (float*)p;
    cudaGetSymbolAddress(&p, g_K);   float* Kb  = (float*)p;
    cudaGetSymbolAddress(&p, g_V);   float* Vb  = (float*)p;
    cudaGetSymbolAddress(&p, g_CTX); float* CTX = (float*)p;

    const int attn_smem = ATTN_SMEM_FLOATS * (int)sizeof(float);
    cudaFuncSetAttribute(attn_kernel,
                         cudaFuncAttributeMaxDynamicSharedMemorySize, attn_smem);

    // 1) dequant
    {
        int t4;
        t4 = QDIM * HID_ / 4;
        dequant_kernel<<<(t4 + 255) / 256, 256>>>(q_qw, q_scale, Wq, HID_, t4);
        t4 = KVDIM * HID_ / 4;
        dequant_kernel<<<(t4 + 255) / 256, 256>>>(k_qw, k_scale, Wk, HID_, t4);
        dequant_kernel<<<(t4 + 255) / 256, 256>>>(v_qw, v_scale, Wv, HID_, t4);
        t4 = HID_ * QDIM / 4;
        dequant_kernel<<<(t4 + 255) / 256, 256>>>(o_qw, o_scale, Wo, QDIM, t4);
    }

    // 2) Q/K/V projections
    gemm_nt_kernel<<<dim3(QDIM / 128,  M_ / 128), 256>>>(hidden, Wq, Qb, M_, QDIM,  HID_);
    gemm_nt_kernel<<<dim3(KVDIM / 128, M_ / 128), 256>>>(hidden, Wk, Kb, M_, KVDIM, HID_);
    gemm_nt_kernel<<<dim3(KVDIM / 128, M_ / 128), 256>>>(hidden, Wv, Vb, M_, KVDIM, HID_);

    // 3) RoPE
    {
        int tot = M_ * (NH_ + NKV_) * 64;
        rope_kernel<<<(tot + 255) / 256, 256>>>(Qb, Kb, cosp, sinp);
    }

    // 4) attention
    attn_kernel<<<dim3(S_ / 64, NH_, B_), 256, attn_smem>>>(Qb, Kb, Vb, CTX);

    // 5) output projection -> d_out
    gemm_nt_kernel<<<dim3(HID_ / 128, M_ / 128), 256>>>(CTX, Wo, out, M_, HID_, QDIM);
}

// round 8
// speedup vs baseline: 2.1402x; 2.1402x over previous
#include <cuda_runtime.h>
#include <cuda_bf16.h>
#include <cstdint>

// ---------------- problem constants ----------------
#define B_    2
#define S_    2048
#define HID_  4096
#define NH_   32
#define NKV_  8
#define HD_   128
#define G_    128
#define M_    (B_*S_)        // 4096 tokens
#define QDIM  (NH_*HD_)      // 4096
#define KVDIM (NKV_*HD_)     // 1024
#define NGRP  (HID_/G_)      // 32 (same for O: QDIM/G_ = 32)

// ---------------- device scratch (no allocations allowed) ----------------
__device__ __nv_bfloat16 g_hidH[M_*HID_],  g_hidL[M_*HID_];
__device__ __nv_bfloat16 g_Wq[QDIM*HID_];
__device__ __nv_bfloat16 g_Wk[KVDIM*HID_];
__device__ __nv_bfloat16 g_Wv[KVDIM*HID_];
__device__ __nv_bfloat16 g_Wo[HID_*QDIM];
__device__ __nv_bfloat16 g_ctxH[M_*QDIM],  g_ctxL[M_*QDIM];
__device__ float g_sTq[NGRP*QDIM];
__device__ float g_sTk[NGRP*KVDIM];
__device__ float g_sTv[NGRP*KVDIM];
__device__ float g_sTo[NGRP*HID_];
__device__ float g_Q [M_*QDIM];
__device__ float g_K [M_*KVDIM];
__device__ float g_V [M_*KVDIM];
__device__ float g_CTX[M_*QDIM];

// ================= low-level helpers (sm_80-compatible PTX only) =========
__device__ __forceinline__ uint32_t smem_u32(const void* p) {
    uint32_t a;
    asm("{ .reg .u64 t; cvta.to.shared.u64 t, %1; cvt.u32.u64 %0, t; }"
        : "=r"(a) : "l"(p));
    return a;
}

#define CPA16(dst, src) \
    asm volatile("cp.async.cg.shared.global [%0], [%1], 16;" \
        :: "r"(dst), "l"(src) : "memory")

#define LDSM4(R0, R1, R2, R3, addr) \
    asm volatile("ldmatrix.sync.aligned.m8n8.x4.shared.b16 {%0,%1,%2,%3}, [%4];" \
        : "=r"(R0), "=r"(R1), "=r"(R2), "=r"(R3) : "r"(addr))

#define MMA16816(d, a0, a1, a2, a3, b0, b1) \
    asm volatile("mma.sync.aligned.m16n8k16.row.col.f32.bf16.bf16.f32 " \
        "{%0,%1,%2,%3}, {%4,%5,%6,%7}, {%8,%9}, {%0,%1,%2,%3};" \
        : "+f"((d)[0]), "+f"((d)[1]), "+f"((d)[2]), "+f"((d)[3]) \
        : "r"(a0), "r"(a1), "r"(a2), "r"(a3), "r"(b0), "r"(b1))

// ---------------- dequant: (qw - 8) -> exact bf16 ------------------------
__global__ void dequant_bf16_kernel(const int* __restrict__ qw,
                                    __nv_bfloat16* __restrict__ w, int total4) {
    int idx = blockIdx.x * blockDim.x + threadIdx.x;
    if (idx >= total4) return;
    int4 q = ((const int4*)qw)[idx];
    ushort4 hv;
    hv.x = __bfloat16_as_ushort(__float2bfloat16((float)(q.x - 8)));
    hv.y = __bfloat16_as_ushort(__float2bfloat16((float)(q.y - 8)));
    hv.z = __bfloat16_as_ushort(__float2bfloat16((float)(q.z - 8)));
    hv.w = __bfloat16_as_ushort(__float2bfloat16((float)(q.w - 8)));
    ((ushort4*)w)[idx] = hv;
}

// ---------------- scale transpose: sT[g][o] = s[o][g] ---------------------
__global__ void scale_T_kernel(const float* __restrict__ s,
                               float* __restrict__ sT, int outdim) {
    int idx = blockIdx.x * blockDim.x + threadIdx.x;
    if (idx >= outdim * NGRP) return;
    int g = idx / outdim;
    int o = idx - g * outdim;
    sT[idx] = s[o * NGRP + g];
}

// ---------------- f32 -> bf16 hi/lo split ---------------------------------
__global__ void split_kernel(const float* __restrict__ x,
                             __nv_bfloat16* __restrict__ xh,
                             __nv_bfloat16* __restrict__ xl, int total4) {
    int idx = blockIdx.x * blockDim.x + threadIdx.x;
    if (idx >= total4) return;
    float4 v = ((const float4*)x)[idx];
    float w[4] = {v.x, v.y, v.z, v.w};
    ushort4 hv, lv;
    unsigned short* hp = &hv.x; unsigned short* lp = &lv.x;
#pragma unroll
    for (int j = 0; j < 4; ++j) {
        __nv_bfloat16 h = __float2bfloat16(w[j]);
        __nv_bfloat16 l = __float2bfloat16(w[j] - __bfloat162float(h));
        hp[j] = __bfloat16_as_ushort(h);
        lp[j] = __bfloat16_as_ushort(l);
    }
    ((ushort4*)xh)[idx] = hv;
    ((ushort4*)xl)[idx] = lv;
}

// ---------------- HMMA GEMM with grouped scales ----------------------------
// C[M,N] = sum_g s[n][g] * (Ah+Al)[M, kg] @ W[N, kg]^T, K = 4096, G = 128.
// CTA: 128x128 tile, BK=64 double-buffered cp.async, 512 threads / 16 warps,
// warp tile 32x32 via m16n8k16 bf16 MMA. Scales applied in fp32 registers
// at each 128-K group boundary (2 chunks).
#define BK      64
#define LDA     72                     // BK + 8 pad (bf16 elems)
#define MAT_B   (128*LDA*2)            // 18432 B per matrix per stage
#define STAGE_B (3*MAT_B)              // Ah, Al, W
#define NCHUNK  (HID_/BK)              // 64
#define GEMM_DSMEM (2*STAGE_B)         // 110592 B

__global__ __launch_bounds__(512, 1)
void gemm_tc(const __nv_bfloat16* __restrict__ Ah,
             const __nv_bfloat16* __restrict__ Al,
             const __nv_bfloat16* __restrict__ Bw,
             const float* __restrict__ sT,
             float* __restrict__ C, int N) {
    extern __shared__ char dsm[];
    const uint32_t sb = smem_u32(dsm);

    const int tid  = threadIdx.x;
    const int wid  = tid >> 5;
    const int lane = tid & 31;
    const int m0 = blockIdx.y << 7, n0 = blockIdx.x << 7;
    const int wm0 = (wid & 3) << 5;    // warp m offset within tile
    const int wn0 = (wid >> 2) << 5;   // warp n offset within tile

    const char* pAh = (const char*)(Ah + (size_t)m0 * HID_);
    const char* pAl = (const char*)(Al + (size_t)m0 * HID_);
    const char* pBw = (const char*)(Bw + (size_t)n0 * HID_);
    const size_t ROWB = HID_ * 2;      // bytes per K-row

    auto load_chunk = [&](int c, int s) {
        const uint32_t base = sb + (uint32_t)s * STAGE_B;
        const size_t koff = (size_t)c * (BK * 2);
#pragma unroll
        for (int i = 0; i < 6; ++i) {
            int u   = i * 512 + tid;
            int mat = u >> 10;             // compile-time per i
            int rem = u & 1023;
            int row = rem >> 3;
            int cu  = rem & 7;
            const char* p = (mat == 0) ? pAh : (mat == 1) ? pAl : pBw;
            uint32_t dst = base + (uint32_t)mat * MAT_B + row * (LDA * 2) + cu * 16;
            CPA16(dst, p + (size_t)row * ROWB + koff + cu * 16);
        }
        asm volatile("cp.async.commit_group;" ::: "memory");
    };

    float acc[2][4][4], part[2][4][4];
#pragma unroll
    for (int mt = 0; mt < 2; ++mt)
#pragma unroll
        for (int nt = 0; nt < 4; ++nt)
#pragma unroll
            for (int r = 0; r < 4; ++r) { acc[mt][nt][r] = 0.f; part[mt][nt][r] = 0.f; }

    // per-thread scale pointer: cols (lane&3)*2 + nt*8 within warp n-tile
    const float* sPtr = sT + (n0 + wn0 + ((lane & 3) << 1));

    const int lrow = lane & 15;
    const int lcolh = (lane >> 4) << 3;   // 0 or 8

    load_chunk(0, 0);

    for (int it = 0; it < NCHUNK; ++it) {
        const int s = it & 1;
        if (it + 1 < NCHUNK) {
            load_chunk(it + 1, s ^ 1);
            asm volatile("cp.async.wait_group 1;" ::: "memory");
        } else {
            asm volatile("cp.async.wait_group 0;" ::: "memory");
        }
        __syncthreads();

        const uint32_t sAh = sb + (uint32_t)s * STAGE_B;
        const uint32_t sAl = sAh + MAT_B;
        const uint32_t sBB = sAh + 2 * MAT_B;

#pragma unroll
        for (int ks = 0; ks < 4; ++ks) {
            const uint32_t col = (ks << 4) + lcolh;   // element col within BK row
            uint32_t ah[2][4], al[2][4];
#pragma unroll
            for (int mt = 0; mt < 2; ++mt) {
                uint32_t ra = (uint32_t)((wm0 + (mt << 4) + lrow) * LDA + col) * 2;
                LDSM4(ah[mt][0], ah[mt][1], ah[mt][2], ah[mt][3], sAh + ra);
                LDSM4(al[mt][0], al[mt][1], al[mt][2], al[mt][3], sAl + ra);
            }
            uint32_t bb[2][4];
#pragma unroll
            for (int p = 0; p < 2; ++p) {
                uint32_t rb = (uint32_t)((wn0 + (p << 4) + lrow) * LDA + col) * 2;
                LDSM4(bb[p][0], bb[p][1], bb[p][2], bb[p][3], sBB + rb);
            }
            // b-frag for ntile nt: pair p = nt/2, half h = nt%2 -> {bb[p][h], bb[p][h+2]}
#pragma unroll
            for (int mt = 0; mt < 2; ++mt)
#pragma unroll
                for (int nt = 0; nt < 4; ++nt) {
                    const int p = nt >> 1, h = nt & 1;
                    MMA16816(part[mt][nt],
                             ah[mt][0], ah[mt][1], ah[mt][2], ah[mt][3],
                             bb[p][h], bb[p][h + 2]);
                    MMA16816(part[mt][nt],
                             al[mt][0], al[mt][1], al[mt][2], al[mt][3],
                             bb[p][h], bb[p][h + 2]);
                }
        }

        if (it & 1) {   // group boundary: fold scale into fp32 accumulators
#pragma unroll
            for (int nt = 0; nt < 4; ++nt) {
                float2 sv = *(const float2*)(sPtr + nt * 8);
#pragma unroll
                for (int mt = 0; mt < 2; ++mt) {
                    acc[mt][nt][0] += sv.x * part[mt][nt][0];
                    acc[mt][nt][1] += sv.y * part[mt][nt][1];
                    acc[mt][nt][2] += sv.x * part[mt][nt][2];
                    acc[mt][nt][3] += sv.y * part[mt][nt][3];
                    part[mt][nt][0] = 0.f; part[mt][nt][1] = 0.f;
                    part[mt][nt][2] = 0.f; part[mt][nt][3] = 0.f;
                }
            }
            sPtr += N;
        }
        __syncthreads();
    }

    // epilogue
    const int colg = n0 + wn0 + ((lane & 3) << 1);
#pragma unroll
    for (int mt = 0; mt < 2; ++mt) {
        const int r0 = m0 + wm0 + (mt << 4) + (lane >> 2);
#pragma unroll
        for (int nt = 0; nt < 4; ++nt) {
            float2 v0 = {acc[mt][nt][0], acc[mt][nt][1]};
            float2 v1 = {acc[mt][nt][2], acc[mt][nt][3]};
            *(float2*)(C + (size_t)r0 * N + colg + nt * 8)       = v0;
            *(float2*)(C + (size_t)(r0 + 8) * N + colg + nt * 8) = v1;
        }
    }
}

// ---------------- RoPE in place on Q and K -------------------------------
__global__ void rope_kernel(float* __restrict__ Q, float* __restrict__ K,
                            const float* __restrict__ cosp,
                            const float* __restrict__ sinp) {
    int t = blockIdx.x * blockDim.x + threadIdx.x;
    const int TOT = M_ * (NH_ + NKV_) * 64;
    if (t >= TOT) return;
    int d = t & 63;
    int r = t >> 6;
    int h = r % (NH_ + NKV_);
    int m = r / (NH_ + NKV_);
    float c1 = cosp[m * HD_ + d],      s1 = sinp[m * HD_ + d];
    float c2 = cosp[m * HD_ + d + 64], s2 = sinp[m * HD_ + d + 64];
    float* base = (h < NH_)
        ? (Q + (size_t)m * QDIM  + h * HD_)
        : (K + (size_t)m * KVDIM + (h - NH_) * HD_);
    float x1 = base[d], x2 = base[d + 64];
    base[d]      = x1 * c1 - x2 * s1;
    base[d + 64] = x2 * c2 + x1 * s2;
}

// ---------------- flash attention (fp32, causal) -------------------------
#define SKS 65
#define ATTN_SMEM_FLOATS (128*SKS + 128*SKS + 64*128 + 64*SKS)

__global__ __launch_bounds__(256) void attn_kernel(
    const float* __restrict__ Q, const float* __restrict__ K,
    const float* __restrict__ V, float* __restrict__ CTX) {
    extern __shared__ float sm[];
    float* Qs = sm;
    float* Ks = Qs + 128 * SKS;
    float* Vs = Ks + 128 * SKS;
    float* Ps = Vs + 64 * 128;

    const float SCALING = 0.08838834764831843f;
    const int qi = blockIdx.x, h = blockIdx.y, b = blockIdx.z;
    const int kvh = h >> 2;
    const int tid = threadIdx.x;
    const int tx = tid & 15, ty = tid >> 4;
    const int q0 = qi << 6;
    const int lrow = tid >> 5;
    const int ld0  = (tid & 31) << 2;

    {
        const float* qb = Q + ((size_t)(b * S_ + q0)) * QDIM + h * HD_;
#pragma unroll
        for (int it = 0; it < 8; ++it) {
            int qr = it * 8 + lrow;
            float4 qv = *(const float4*)(qb + (size_t)qr * QDIM + ld0);
            Qs[(ld0 + 0) * SKS + qr] = qv.x;
            Qs[(ld0 + 1) * SKS + qr] = qv.y;
            Qs[(ld0 + 2) * SKS + qr] = qv.z;
            Qs[(ld0 + 3) * SKS + qr] = qv.w;
        }
    }

    float mrow[4], lsum[4], o[4][8];
#pragma unroll
    for (int i = 0; i < 4; ++i) {
        mrow[i] = -1e30f; lsum[i] = 0.f;
#pragma unroll
        for (int jj = 0; jj < 8; ++jj) o[i][jj] = 0.f;
    }

    const float* kb = K + ((size_t)(b * S_)) * KVDIM + kvh * HD_;
    const float* vb = V + ((size_t)(b * S_)) * KVDIM + kvh * HD_;

    for (int kt = 0; kt <= qi; ++kt) {
        const int k0 = kt << 6;
        __syncthreads();
#pragma unroll
        for (int it = 0; it < 8; ++it) {
            int kr = it * 8 + lrow;
            float4 kv4 = *(const float4*)(kb + (size_t)(k0 + kr) * KVDIM + ld0);
            Ks[(ld0 + 0) * SKS + kr] = kv4.x;
            Ks[(ld0 + 1) * SKS + kr] = kv4.y;
            Ks[(ld0 + 2) * SKS + kr] = kv4.z;
            Ks[(ld0 + 3) * SKS + kr] = kv4.w;
            float4 vv4 = *(const float4*)(vb + (size_t)(k0 + kr) * KVDIM + ld0);
            *(float4*)&Vs[kr * 128 + ld0] = vv4;
        }
        __syncthreads();

        float sc[4][4];
#pragma unroll
        for (int i = 0; i < 4; ++i)
#pragma unroll
            for (int j = 0; j < 4; ++j) sc[i][j] = 0.f;
        for (int d = 0; d < 128; ++d) {
            float qv[4], kr4[4];
#pragma unroll
            for (int i = 0; i < 4; ++i) qv[i]  = Qs[d * SKS + ty * 4 + i];
#pragma unroll
            for (int j = 0; j < 4; ++j) kr4[j] = Ks[d * SKS + tx * 4 + j];
#pragma unroll
            for (int i = 0; i < 4; ++i)
#pragma unroll
                for (int j = 0; j < 4; ++j)
                    sc[i][j] = fmaf(qv[i], kr4[j], sc[i][j]);
        }

        const bool diag = (kt == qi);
#pragma unroll
        for (int i = 0; i < 4; ++i)
#pragma unroll
            for (int j = 0; j < 4; ++j) {
                float s = sc[i][j] * SCALING;
                if (diag && (k0 + tx * 4 + j) > (q0 + ty * 4 + i)) s = -1e30f;
                sc[i][j] = s;
            }

#pragma unroll
        for (int i = 0; i < 4; ++i) {
            float mn = fmaxf(fmaxf(sc[i][0], sc[i][1]), fmaxf(sc[i][2], sc[i][3]));
#pragma unroll
            for (int off = 8; off > 0; off >>= 1)
                mn = fmaxf(mn, __shfl_xor_sync(0xffffffffu, mn, off, 16));
            mn = fmaxf(mn, mrow[i]);
            float corr = __expf(mrow[i] - mn);
            mrow[i] = mn;
            float rs = 0.f;
#pragma unroll
            for (int j = 0; j < 4; ++j) {
                float p = __expf(sc[i][j] - mn);
                sc[i][j] = p;
                rs += p;
            }
#pragma unroll
            for (int off = 8; off > 0; off >>= 1)
                rs += __shfl_xor_sync(0xffffffffu, rs, off, 16);
            lsum[i] = lsum[i] * corr + rs;
#pragma unroll
            for (int jj = 0; jj < 8; ++jj) o[i][jj] *= corr;
        }

#pragma unroll
        for (int i = 0; i < 4; ++i)
#pragma unroll
            for (int j = 0; j < 4; ++j)
                Ps[(ty * 4 + i) * SKS + tx * 4 + j] = sc[i][j];
        __syncthreads();

#pragma unroll 2
        for (int c = 0; c < 64; ++c) {
            float p0 = Ps[(ty * 4 + 0) * SKS + c];
            float p1 = Ps[(ty * 4 + 1) * SKS + c];
            float p2 = Ps[(ty * 4 + 2) * SKS + c];
            float p3 = Ps[(ty * 4 + 3) * SKS + c];
            float4 v0 = *(const float4*)&Vs[c * 128 + tx * 8];
            float4 v1 = *(const float4*)&Vs[c * 128 + tx * 8 + 4];
            float vr[8] = {v0.x, v0.y, v0.z, v0.w, v1.x, v1.y, v1.z, v1.w};
            float pr[4] = {p0, p1, p2, p3};
#pragma unroll
            for (int i = 0; i < 4; ++i)
#pragma unroll
                for (int jj = 0; jj < 8; ++jj)
                    o[i][jj] = fmaf(pr[i], vr[jj], o[i][jj]);
        }
    }

#pragma unroll
    for (int i = 0; i < 4; ++i) {
        int q = q0 + ty * 4 + i;
        float iv = 1.0f / lsum[i];
        float* outp = CTX + ((size_t)(b * S_ + q)) * QDIM + h * HD_ + tx * 8;
        float4 r0 = {o[i][0] * iv, o[i][1] * iv, o[i][2] * iv, o[i][3] * iv};
        float4 r1 = {o[i][4] * iv, o[i][5] * iv, o[i][6] * iv, o[i][7] * iv};
        *(float4*)outp       = r0;
        *(float4*)(outp + 4) = r1;
    }
}

// ---------------- launch --------------------------------------------------
extern "C" void kernel_launch(void* const* d_in, const int* in_sizes, int n_in,
                              void* d_out, int out_size) {
    const float* hidden  = (const float*)d_in[0];
    const float* cosp    = (const float*)d_in[1];
    const float* sinp    = (const float*)d_in[2];
    // d_in[3] attention_mask: pure causal -> applied analytically
    const int*   q_qw    = (const int*)  d_in[4];
    const float* q_scale = (const float*)d_in[5];
    const int*   k_qw    = (const int*)  d_in[6];
    const float* k_scale = (const float*)d_in[7];
    const int*   v_qw    = (const int*)  d_in[8];
    const float* v_scale = (const float*)d_in[9];
    const int*   o_qw    = (const int*)  d_in[10];
    const float* o_scale = (const float*)d_in[11];
    float* out = (float*)d_out;

    void* p;
    cudaGetSymbolAddress(&p, g_hidH); __nv_bfloat16* hidH = (__nv_bfloat16*)p;
    cudaGetSymbolAddress(&p, g_hidL); __nv_bfloat16* hidL = (__nv_bfloat16*)p;
    cudaGetSymbolAddress(&p, g_Wq);   __nv_bfloat16* Wq   = (__nv_bfloat16*)p;
    cudaGetSymbolAddress(&p, g_Wk);   __nv_bfloat16* Wk   = (__nv_bfloat16*)p;
    cudaGetSymbolAddress(&p, g_Wv);   __nv_bfloat16* Wv   = (__nv_bfloat16*)p;
    cudaGetSymbolAddress(&p, g_Wo);   __nv_bfloat16* Wo   = (__nv_bfloat16*)p;
    cudaGetSymbolAddress(&p, g_ctxH); __nv_bfloat16* ctxH = (__nv_bfloat16*)p;
    cudaGetSymbolAddress(&p, g_ctxL); __nv_bfloat16* ctxL = (__nv_bfloat16*)p;
    cudaGetSymbolAddress(&p, g_sTq);  float* sTq = (float*)p;
    cudaGetSymbolAddress(&p, g_sTk);  float* sTk = (float*)p;
    cudaGetSymbolAddress(&p, g_sTv);  float* sTv = (float*)p;
    cudaGetSymbolAddress(&p, g_sTo);  float* sTo = (float*)p;
    cudaGetSymbolAddress(&p, g_Q);    float* Qb  = (float*)p;
    cudaGetSymbolAddress(&p, g_K);    float* Kb  = (float*)p;
    cudaGetSymbolAddress(&p, g_V);    float* Vb  = (float*)p;
    cudaGetSymbolAddress(&p, g_CTX);  float* CTX = (float*)p;

    const int attn_smem = ATTN_SMEM_FLOATS * (int)sizeof(float);
    cudaFuncSetAttribute(attn_kernel,
                         cudaFuncAttributeMaxDynamicSharedMemorySize, attn_smem);
    cudaFuncSetAttribute(gemm_tc,
                         cudaFuncAttributeMaxDynamicSharedMemorySize, GEMM_DSMEM);

    // 1) dequant weights to exact bf16 (q-8), transpose scales
    {
        int t4;
        t4 = QDIM * HID_ / 4;
        dequant_bf16_kernel<<<(t4 + 255) / 256, 256>>>(q_qw, Wq, t4);
        t4 = KVDIM * HID_ / 4;
        dequant_bf16_kernel<<<(t4 + 255) / 256, 256>>>(k_qw, Wk, t4);
        dequant_bf16_kernel<<<(t4 + 255) / 256, 256>>>(v_qw, Wv, t4);
        t4 = HID_ * QDIM / 4;
        dequant_bf16_kernel<<<(t4 + 255) / 256, 256>>>(o_qw, Wo, t4);

        int ts;
        ts = QDIM * NGRP;
        scale_T_kernel<<<(ts + 255) / 256, 256>>>(q_scale, sTq, QDIM);
        ts = KVDIM * NGRP;
        scale_T_kernel<<<(ts + 255) / 256, 256>>>(k_scale, sTk, KVDIM);
        scale_T_kernel<<<(ts + 255) / 256, 256>>>(v_scale, sTv, KVDIM);
        ts = HID_ * NGRP;
        scale_T_kernel<<<(ts + 255) / 256, 256>>>(o_scale, sTo, HID_);
    }

    // 2) split hidden states into bf16 hi/lo
    {
        int t4 = M_ * HID_ / 4;
        split_kernel<<<(t4 + 255) / 256, 256>>>(hidden, hidH, hidL, t4);
    }

    // 3) Q/K/V projections on HMMA tensor cores
    gemm_tc<<<dim3(QDIM / 128,  M_ / 128), 512, GEMM_DSMEM>>>(hidH, hidL, Wq, sTq, Qb, QDIM);
    gemm_tc<<<dim3(KVDIM / 128, M_ / 128), 512, GEMM_DSMEM>>>(hidH, hidL, Wk, sTk, Kb, KVDIM);
    gemm_tc<<<dim3(KVDIM / 128, M_ / 128), 512, GEMM_DSMEM>>>(hidH, hidL, Wv, sTv, Vb, KVDIM);

    // 4) RoPE
    {
        int tot = M_ * (NH_ + NKV_) * 64;
        rope_kernel<<<(tot + 255) / 256, 256>>>(Qb, Kb, cosp, sinp);
    }

    // 5) attention (fp32 flash)
    attn_kernel<<<dim3(S_ / 64, NH_, B_), 256, attn_smem>>>(Qb, Kb, Vb, CTX);

    // 6) split ctx, O-projection on HMMA -> d_out
    {
        int t4 = M_ * QDIM / 4;
        split_kernel<<<(t4 + 255) / 256, 256>>>(CTX, ctxH, ctxL, t4);
    }
    gemm_tc<<<dim3(HID_ / 128, M_ / 128), 512, GEMM_DSMEM>>>(ctxH, ctxL, Wo, sTo, out, HID_);
}

// round 9
// speedup vs baseline: 3.7866x; 1.7693x over previous
#include <cuda_runtime.h>
#include <cuda_bf16.h>
#include <cstdint>

// ---------------- problem constants ----------------
#define B_    2
#define S_    2048
#define HID_  4096
#define NH_   32
#define NKV_  8
#define HD_   128
#define G_    128
#define M_    (B_*S_)        // 4096 tokens
#define QDIM  (NH_*HD_)      // 4096
#define KVDIM (NKV_*HD_)     // 1024
#define NGRP  (HID_/G_)      // 32

// ---------------- device scratch (no allocations allowed) ----------------
__device__ __nv_bfloat16 g_hidH[M_*HID_],  g_hidL[M_*HID_];
__device__ __nv_bfloat16 g_Wq[QDIM*HID_];
__device__ __nv_bfloat16 g_Wk[KVDIM*HID_];
__device__ __nv_bfloat16 g_Wv[KVDIM*HID_];
__device__ __nv_bfloat16 g_Wo[HID_*QDIM];
__device__ __nv_bfloat16 g_ctxH[M_*QDIM],  g_ctxL[M_*QDIM];
__device__ float g_sTq[NGRP*QDIM];
__device__ float g_sTk[NGRP*KVDIM];
__device__ float g_sTv[NGRP*KVDIM];
__device__ float g_sTo[NGRP*HID_];
__device__ float g_Q [M_*QDIM];
__device__ float g_K [M_*KVDIM];
__device__ float g_V [M_*KVDIM];
__device__ __nv_bfloat16 g_Qh[M_*QDIM],  g_Ql[M_*QDIM];
__device__ __nv_bfloat16 g_Kh[M_*KVDIM], g_Kl[M_*KVDIM];
__device__ __nv_bfloat16 g_Vh[M_*KVDIM], g_Vl[M_*KVDIM];

// ================= low-level helpers (sm_80-compatible PTX only) =========
__device__ __forceinline__ uint32_t smem_u32(const void* p) {
    uint32_t a;
    asm("{ .reg .u64 t; cvta.to.shared.u64 t, %1; cvt.u32.u64 %0, t; }"
        : "=r"(a) : "l"(p));
    return a;
}

#define CPA16(dst, src) \
    asm volatile("cp.async.cg.shared.global [%0], [%1], 16;" \
        :: "r"(dst), "l"(src) : "memory")

#define LDSM4(R0, R1, R2, R3, addr) \
    asm volatile("ldmatrix.sync.aligned.m8n8.x4.shared.b16 {%0,%1,%2,%3}, [%4];" \
        : "=r"(R0), "=r"(R1), "=r"(R2), "=r"(R3) : "r"(addr))

#define LDSM4T(R0, R1, R2, R3, addr) \
    asm volatile("ldmatrix.sync.aligned.m8n8.x4.trans.shared.b16 {%0,%1,%2,%3}, [%4];" \
        : "=r"(R0), "=r"(R1), "=r"(R2), "=r"(R3) : "r"(addr))

#define MMA16816(d, a0, a1, a2, a3, b0, b1) \
    asm volatile("mma.sync.aligned.m16n8k16.row.col.f32.bf16.bf16.f32 " \
        "{%0,%1,%2,%3}, {%4,%5,%6,%7}, {%8,%9}, {%0,%1,%2,%3};" \
        : "+f"((d)[0]), "+f"((d)[1]), "+f"((d)[2]), "+f"((d)[3]) \
        : "r"(a0), "r"(a1), "r"(a2), "r"(a3), "r"(b0), "r"(b1))

__device__ __forceinline__ float fast_exp2(float x) {
    float r;
    asm("ex2.approx.ftz.f32 %0, %1;" : "=f"(r) : "f"(x));
    return r;
}

// ---------------- dequant: (qw - 8) -> exact bf16 ------------------------
__global__ void dequant_bf16_kernel(const int* __restrict__ qw,
                                    __nv_bfloat16* __restrict__ w, int total4) {
    int idx = blockIdx.x * blockDim.x + threadIdx.x;
    if (idx >= total4) return;
    int4 q = ((const int4*)qw)[idx];
    ushort4 hv;
    hv.x = __bfloat16_as_ushort(__float2bfloat16((float)(q.x - 8)));
    hv.y = __bfloat16_as_ushort(__float2bfloat16((float)(q.y - 8)));
    hv.z = __bfloat16_as_ushort(__float2bfloat16((float)(q.z - 8)));
    hv.w = __bfloat16_as_ushort(__float2bfloat16((float)(q.w - 8)));
    ((ushort4*)w)[idx] = hv;
}

// ---------------- scale transpose: sT[g][o] = s[o][g] ---------------------
__global__ void scale_T_kernel(const float* __restrict__ s,
                               float* __restrict__ sT, int outdim) {
    int idx = blockIdx.x * blockDim.x + threadIdx.x;
    if (idx >= outdim * NGRP) return;
    int g = idx / outdim;
    int o = idx - g * outdim;
    sT[idx] = s[o * NGRP + g];
}

// ---------------- f32 -> bf16 hi/lo split ---------------------------------
__global__ void split_kernel(const float* __restrict__ x,
                             __nv_bfloat16* __restrict__ xh,
                             __nv_bfloat16* __restrict__ xl, int total4) {
    int idx = blockIdx.x * blockDim.x + threadIdx.x;
    if (idx >= total4) return;
    float4 v = ((const float4*)x)[idx];
    float w[4] = {v.x, v.y, v.z, v.w};
    ushort4 hv, lv;
    unsigned short* hp = &hv.x; unsigned short* lp = &lv.x;
#pragma unroll
    for (int j = 0; j < 4; ++j) {
        __nv_bfloat16 h = __float2bfloat16(w[j]);
        __nv_bfloat16 l = __float2bfloat16(w[j] - __bfloat162float(h));
        hp[j] = __bfloat16_as_ushort(h);
        lp[j] = __bfloat16_as_ushort(l);
    }
    ((ushort4*)xh)[idx] = hv;
    ((ushort4*)xl)[idx] = lv;
}

// ---------------- RoPE + hi/lo split for Q and K ---------------------------
__global__ void rope_split_kernel(const float* __restrict__ Q,
                                  const float* __restrict__ K,
                                  const float* __restrict__ cosp,
                                  const float* __restrict__ sinp,
                                  __nv_bfloat16* __restrict__ Qh,
                                  __nv_bfloat16* __restrict__ Ql,
                                  __nv_bfloat16* __restrict__ Kh,
                                  __nv_bfloat16* __restrict__ Kl) {
    int t = blockIdx.x * blockDim.x + threadIdx.x;
    const int TOT = M_ * (NH_ + NKV_) * 64;
    if (t >= TOT) return;
    int d = t & 63;
    int r = t >> 6;
    int h = r % (NH_ + NKV_);
    int m = r / (NH_ + NKV_);
    float c1 = cosp[m * HD_ + d],      s1 = sinp[m * HD_ + d];
    float c2 = cosp[m * HD_ + d + 64], s2 = sinp[m * HD_ + d + 64];
    const float* base;
    __nv_bfloat16 *oh, *ol;
    size_t off;
    if (h < NH_) {
        off = (size_t)m * QDIM + h * HD_;
        base = Q + off; oh = Qh; ol = Ql;
    } else {
        off = (size_t)m * KVDIM + (h - NH_) * HD_;
        base = K + off; oh = Kh; ol = Kl;
    }
    float x1 = base[d], x2 = base[d + 64];
    float y1 = x1 * c1 - x2 * s1;
    float y2 = x2 * c2 + x1 * s2;
    __nv_bfloat16 h1 = __float2bfloat16(y1);
    __nv_bfloat16 h2 = __float2bfloat16(y2);
    oh[off + d]      = h1;
    oh[off + d + 64] = h2;
    ol[off + d]      = __float2bfloat16(y1 - __bfloat162float(h1));
    ol[off + d + 64] = __float2bfloat16(y2 - __bfloat162float(h2));
}

// ---------------- HMMA GEMM with grouped scales (3-stage pipeline) --------
#define BK      64
#define LDA     72
#define MAT_B   (128*LDA*2)            // 18432 B per matrix per stage
#define STAGE_B (3*MAT_B)              // Ah, Al, W
#define NCHUNK  (HID_/BK)              // 64
#define GEMM_DSMEM (3*STAGE_B)         // 165888 B

__global__ __launch_bounds__(512, 1)
void gemm_tc(const __nv_bfloat16* __restrict__ Ah,
             const __nv_bfloat16* __restrict__ Al,
             const __nv_bfloat16* __restrict__ Bw,
             const float* __restrict__ sT,
             float* __restrict__ C, int N) {
    extern __shared__ char dsm[];
    const uint32_t sb = smem_u32(dsm);

    const int tid  = threadIdx.x;
    const int wid  = tid >> 5;
    const int lane = tid & 31;
    const int m0 = blockIdx.y << 7, n0 = blockIdx.x << 7;
    const int wm0 = (wid & 3) << 5;
    const int wn0 = (wid >> 2) << 5;

    const char* pAh = (const char*)(Ah + (size_t)m0 * HID_);
    const char* pAl = (const char*)(Al + (size_t)m0 * HID_);
    const char* pBw = (const char*)(Bw + (size_t)n0 * HID_);
    const size_t ROWB = HID_ * 2;

    auto load_chunk = [&](int c, int st) {
        const uint32_t base = sb + (uint32_t)st * STAGE_B;
        const size_t koff = (size_t)c * (BK * 2);
#pragma unroll
        for (int i = 0; i < 6; ++i) {
            int u   = i * 512 + tid;
            int mat = u >> 10;
            int rem = u & 1023;
            int row = rem >> 3;
            int cu  = rem & 7;
            const char* p = (mat == 0) ? pAh : (mat == 1) ? pAl : pBw;
            uint32_t dst = base + (uint32_t)mat * MAT_B + row * (LDA * 2) + cu * 16;
            CPA16(dst, p + (size_t)row * ROWB + koff + cu * 16);
        }
        asm volatile("cp.async.commit_group;" ::: "memory");
    };

    float acc[2][4][4], part[2][4][4];
#pragma unroll
    for (int mt = 0; mt < 2; ++mt)
#pragma unroll
        for (int nt = 0; nt < 4; ++nt)
#pragma unroll
            for (int r = 0; r < 4; ++r) { acc[mt][nt][r] = 0.f; part[mt][nt][r] = 0.f; }

    const float* sPtr = sT + (n0 + wn0 + ((lane & 3) << 1));

    const int lrow = lane & 15;
    const int lcolh = (lane >> 4) << 3;

    load_chunk(0, 0);
    load_chunk(1, 1);

    int st = 0;
    for (int it = 0; it < NCHUNK; ++it) {
        if (it + 1 < NCHUNK) {
            asm volatile("cp.async.wait_group 1;" ::: "memory");
        } else {
            asm volatile("cp.async.wait_group 0;" ::: "memory");
        }
        __syncthreads();

        int s2 = st + 2; if (s2 >= 3) s2 -= 3;
        if (it + 2 < NCHUNK) load_chunk(it + 2, s2);

        const uint32_t sAh = sb + (uint32_t)st * STAGE_B;
        const uint32_t sAl = sAh + MAT_B;
        const uint32_t sBB = sAh + 2 * MAT_B;

#pragma unroll
        for (int ks = 0; ks < 4; ++ks) {
            const uint32_t col = (ks << 4) + lcolh;
            uint32_t ah[2][4], al[2][4];
#pragma unroll
            for (int mt = 0; mt < 2; ++mt) {
                uint32_t ra = (uint32_t)((wm0 + (mt << 4) + lrow) * LDA + col) * 2;
                LDSM4(ah[mt][0], ah[mt][1], ah[mt][2], ah[mt][3], sAh + ra);
                LDSM4(al[mt][0], al[mt][1], al[mt][2], al[mt][3], sAl + ra);
            }
            uint32_t bb[2][4];
#pragma unroll
            for (int p = 0; p < 2; ++p) {
                uint32_t rb = (uint32_t)((wn0 + (p << 4) + lrow) * LDA + col) * 2;
                LDSM4(bb[p][0], bb[p][1], bb[p][2], bb[p][3], sBB + rb);
            }
#pragma unroll
            for (int mt = 0; mt < 2; ++mt)
#pragma unroll
                for (int nt = 0; nt < 4; ++nt) {
                    const int p = nt >> 1, h = nt & 1;
                    MMA16816(part[mt][nt],
                             ah[mt][0], ah[mt][1], ah[mt][2], ah[mt][3],
                             bb[p][h], bb[p][h + 2]);
                    MMA16816(part[mt][nt],
                             al[mt][0], al[mt][1], al[mt][2], al[mt][3],
                             bb[p][h], bb[p][h + 2]);
                }
        }

        if (it & 1) {
#pragma unroll
            for (int nt = 0; nt < 4; ++nt) {
                float2 sv = *(const float2*)(sPtr + nt * 8);
#pragma unroll
                for (int mt = 0; mt < 2; ++mt) {
                    acc[mt][nt][0] += sv.x * part[mt][nt][0];
                    acc[mt][nt][1] += sv.y * part[mt][nt][1];
                    acc[mt][nt][2] += sv.x * part[mt][nt][2];
                    acc[mt][nt][3] += sv.y * part[mt][nt][3];
                    part[mt][nt][0] = 0.f; part[mt][nt][1] = 0.f;
                    part[mt][nt][2] = 0.f; part[mt][nt][3] = 0.f;
                }
            }
            sPtr += N;
        }

        ++st; if (st == 3) st = 0;
    }

    const int colg = n0 + wn0 + ((lane & 3) << 1);
#pragma unroll
    for (int mt = 0; mt < 2; ++mt) {
        const int r0 = m0 + wm0 + (mt << 4) + (lane >> 2);
#pragma unroll
        for (int nt = 0; nt < 4; ++nt) {
            float2 v0 = {acc[mt][nt][0], acc[mt][nt][1]};
            float2 v1 = {acc[mt][nt][2], acc[mt][nt][3]};
            *(float2*)(C + (size_t)r0 * N + colg + nt * 8)       = v0;
            *(float2*)(C + (size_t)(r0 + 8) * N + colg + nt * 8) = v1;
        }
    }
}

// ---------------- HMMA flash attention (causal) ----------------------------
// CTA: 128 q-rows x one head x batch; 8 warps (warp = 16 q-rows).
// K/V tiles 64 x 128 hi/lo, double-buffered cp.async. Q frags in registers.
// 3-term QK (QhKh+QhKl+QlKh) and 3-term PV (PhVh+PhVl+PlVh).
#define LDK 136
#define LDP 72
#define KMAT_B (64*LDK*2)              // 17408
#define KV_STAGE_B (4*KMAT_B)          // 69632
#define ATTN_PH_OFF (2*KV_STAGE_B)     // 139264
#define ATTN_PL_OFF (ATTN_PH_OFF + 128*LDP*2)
#define ATTN_SMEM_B (ATTN_PL_OFF + 128*LDP*2)   // 176128

__global__ __launch_bounds__(256, 1)
void attn_tc(const __nv_bfloat16* __restrict__ Qhg, const __nv_bfloat16* __restrict__ Qlg,
             const __nv_bfloat16* __restrict__ Khg, const __nv_bfloat16* __restrict__ Klg,
             const __nv_bfloat16* __restrict__ Vhg, const __nv_bfloat16* __restrict__ Vlg,
             __nv_bfloat16* __restrict__ ctxH, __nv_bfloat16* __restrict__ ctxL) {
    extern __shared__ char smc[];
    const uint32_t sb = smem_u32(smc);

    const int qi = blockIdx.x, h = blockIdx.y, b = blockIdx.z;
    const int kvh = h >> 2;
    const int tid = threadIdx.x, wid = tid >> 5, lane = tid & 31;
    const int q0 = qi << 7;
    const int nk = 2 * qi + 2;

    const int lrow  = lane & 15;
    const int lcol8 = (lane >> 4) << 3;
    const int trow  = lane >> 2;          // 0..7
    const int tcol  = (lane & 3) << 1;    // 0,2,4,6

    // SCALING/sqrt(d) folded with log2(e): softmax computed in base 2
    const float SC2 = 0.08838834764831843f * 1.4426950408889634f;

    // ---- stage Q tile, build register fragments (hi then lo) ----
    uint32_t qhf[8][4], qlf[8][4];
    {
        const __nv_bfloat16* srcH = Qhg + ((size_t)(b * S_ + q0)) * QDIM + h * HD_;
        const __nv_bfloat16* srcL = Qlg + ((size_t)(b * S_ + q0)) * QDIM + h * HD_;
#pragma unroll
        for (int pass = 0; pass < 2; ++pass) {
            const char* src = (const char*)(pass ? srcL : srcH);
#pragma unroll
            for (int i = 0; i < 8; ++i) {
                int u = tid + (i << 8);
                int row = u >> 4, cu = u & 15;
                *(uint4*)(smc + row * (LDK * 2) + cu * 16) =
                    *(const uint4*)(src + (size_t)row * (QDIM * 2) + cu * 16);
            }
            __syncthreads();
#pragma unroll
            for (int ks = 0; ks < 8; ++ks) {
                uint32_t a = sb + (uint32_t)((wid * 16 + lrow) * LDK + ks * 16 + lcol8) * 2;
                if (pass == 0) LDSM4(qhf[ks][0], qhf[ks][1], qhf[ks][2], qhf[ks][3], a);
                else           LDSM4(qlf[ks][0], qlf[ks][1], qlf[ks][2], qlf[ks][3], a);
            }
            __syncthreads();
        }
    }

    float m2[2] = {-1e30f, -1e30f}, l2[2] = {0.f, 0.f};
    float o[16][4];
#pragma unroll
    for (int i = 0; i < 16; ++i)
#pragma unroll
        for (int j = 0; j < 4; ++j) o[i][j] = 0.f;

    const char* kh_g = (const char*)(Khg + ((size_t)(b * S_)) * KVDIM + kvh * HD_);
    const char* kl_g = (const char*)(Klg + ((size_t)(b * S_)) * KVDIM + kvh * HD_);
    const char* vh_g = (const char*)(Vhg + ((size_t)(b * S_)) * KVDIM + kvh * HD_);
    const char* vl_g = (const char*)(Vlg + ((size_t)(b * S_)) * KVDIM + kvh * HD_);
    const size_t KROWB = KVDIM * 2;

    auto prefetch = [&](int kt, int stg) {
        const uint32_t base = sb + (uint32_t)stg * KV_STAGE_B;
        const size_t g0 = (size_t)(kt << 6) * KROWB;
#pragma unroll
        for (int i = 0; i < 16; ++i) {
            int u = tid + (i << 8);
            int mat = u >> 10;
            int rem = u & 1023, row = rem >> 4, cu = rem & 15;
            const char* g = (mat == 0) ? kh_g : (mat == 1) ? kl_g
                          : (mat == 2) ? vh_g : vl_g;
            CPA16(base + (uint32_t)mat * KMAT_B + row * (LDK * 2) + cu * 16,
                  g + g0 + (size_t)row * KROWB + cu * 16);
        }
        asm volatile("cp.async.commit_group;" ::: "memory");
    };

    prefetch(0, 0);

    for (int kt = 0; kt < nk; ++kt) {
        const int stg = kt & 1;
        const int k0 = kt << 6;
        if (kt + 1 < nk) {
            prefetch(kt + 1, stg ^ 1);
            asm volatile("cp.async.wait_group 1;" ::: "memory");
        } else {
            asm volatile("cp.async.wait_group 0;" ::: "memory");
        }
        __syncthreads();

        const uint32_t kv = sb + (uint32_t)stg * KV_STAGE_B;

        // ---- scores: S = Qh Kh^T + Qh Kl^T + Ql Kh^T ----
        float sc[8][4];
#pragma unroll
        for (int i = 0; i < 8; ++i)
#pragma unroll
            for (int j = 0; j < 4; ++j) sc[i][j] = 0.f;

#pragma unroll
        for (int ks = 0; ks < 8; ++ks) {
#pragma unroll
            for (int p = 0; p < 4; ++p) {
                uint32_t ka = kv + (uint32_t)((p * 16 + lrow) * LDK + ks * 16 + lcol8) * 2;
                uint32_t kh4[4], kl4[4];
                LDSM4(kh4[0], kh4[1], kh4[2], kh4[3], ka);
                LDSM4(kl4[0], kl4[1], kl4[2], kl4[3], ka + KMAT_B);
                MMA16816(sc[2*p], qhf[ks][0], qhf[ks][1], qhf[ks][2], qhf[ks][3], kh4[0], kh4[2]);
                MMA16816(sc[2*p], qhf[ks][0], qhf[ks][1], qhf[ks][2], qhf[ks][3], kl4[0], kl4[2]);
                MMA16816(sc[2*p], qlf[ks][0], qlf[ks][1], qlf[ks][2], qlf[ks][3], kh4[0], kh4[2]);
                MMA16816(sc[2*p+1], qhf[ks][0], qhf[ks][1], qhf[ks][2], qhf[ks][3], kh4[1], kh4[3]);
                MMA16816(sc[2*p+1], qhf[ks][0], qhf[ks][1], qhf[ks][2], qhf[ks][3], kl4[1], kl4[3]);
                MMA16816(sc[2*p+1], qlf[ks][0], qlf[ks][1], qlf[ks][2], qlf[ks][3], kh4[1], kh4[3]);
            }
        }

        // ---- scale + causal mask (only needed on the last two k-tiles) ----
        const bool needMask = (kt >= nk - 2);
#pragma unroll
        for (int h2 = 0; h2 < 2; ++h2) {
            const int grow = q0 + wid * 16 + trow + 8 * h2;
#pragma unroll
            for (int nt = 0; nt < 8; ++nt)
#pragma unroll
                for (int j = 0; j < 2; ++j) {
                    float x = sc[nt][2*h2 + j] * SC2;
                    if (needMask && (k0 + nt * 8 + tcol + j) > grow) x = -1e30f;
                    sc[nt][2*h2 + j] = x;
                }
        }

        // ---- online softmax (base-2), P -> hi/lo bf16 into smem ----
#pragma unroll
        for (int h2 = 0; h2 < 2; ++h2) {
            float mx = -1e30f;
#pragma unroll
            for (int nt = 0; nt < 8; ++nt) {
                mx = fmaxf(mx, sc[nt][2*h2]);
                mx = fmaxf(mx, sc[nt][2*h2 + 1]);
            }
            mx = fmaxf(mx, __shfl_xor_sync(0xffffffffu, mx, 1));
            mx = fmaxf(mx, __shfl_xor_sync(0xffffffffu, mx, 2));
            float mnew = fmaxf(m2[h2], mx);
            float corr = fast_exp2(m2[h2] - mnew);
            m2[h2] = mnew;

            float rs = 0.f;
            const int prow = wid * 16 + trow + 8 * h2;
#pragma unroll
            for (int nt = 0; nt < 8; ++nt) {
                float p0 = fast_exp2(sc[nt][2*h2]     - mnew);
                float p1 = fast_exp2(sc[nt][2*h2 + 1] - mnew);
                rs += p0 + p1;
                __nv_bfloat16 h0 = __float2bfloat16(p0);
                __nv_bfloat16 h1 = __float2bfloat16(p1);
                __nv_bfloat16 l0 = __float2bfloat16(p0 - __bfloat162float(h0));
                __nv_bfloat16 l1 = __float2bfloat16(p1 - __bfloat162float(h1));
                __nv_bfloat162 hp; hp.x = h0; hp.y = h1;
                __nv_bfloat162 lp; lp.x = l0; lp.y = l1;
                *(__nv_bfloat162*)(smc + ATTN_PH_OFF + (prow * LDP + nt * 8 + tcol) * 2) = hp;
                *(__nv_bfloat162*)(smc + ATTN_PL_OFF + (prow * LDP + nt * 8 + tcol) * 2) = lp;
            }
            rs += __shfl_xor_sync(0xffffffffu, rs, 1);
            rs += __shfl_xor_sync(0xffffffffu, rs, 2);
            l2[h2] = l2[h2] * corr + rs;
#pragma unroll
            for (int nt = 0; nt < 16; ++nt) {
                o[nt][2*h2]     *= corr;
                o[nt][2*h2 + 1] *= corr;
            }
        }
        __syncwarp();

        // ---- O += Ph Vh + Ph Vl + Pl Vh ----
#pragma unroll
        for (int ks2 = 0; ks2 < 4; ++ks2) {
            uint32_t pa = sb + ATTN_PH_OFF +
                (uint32_t)((wid * 16 + lrow) * LDP + ks2 * 16 + lcol8) * 2;
            uint32_t ph4[4], pl4[4];
            LDSM4(ph4[0], ph4[1], ph4[2], ph4[3], pa);
            LDSM4(pl4[0], pl4[1], pl4[2], pl4[3], pa + (ATTN_PL_OFF - ATTN_PH_OFF));
#pragma unroll
            for (int nd = 0; nd < 8; ++nd) {
                uint32_t va = kv + 2 * KMAT_B +
                    (uint32_t)((ks2 * 16 + lrow) * LDK + nd * 16 + lcol8) * 2;
                uint32_t vh4[4], vl4[4];
                LDSM4T(vh4[0], vh4[1], vh4[2], vh4[3], va);
                LDSM4T(vl4[0], vl4[1], vl4[2], vl4[3], va + KMAT_B);
                MMA16816(o[2*nd], ph4[0], ph4[1], ph4[2], ph4[3], vh4[0], vh4[1]);
                MMA16816(o[2*nd], ph4[0], ph4[1], ph4[2], ph4[3], vl4[0], vl4[1]);
                MMA16816(o[2*nd], pl4[0], pl4[1], pl4[2], pl4[3], vh4[0], vh4[1]);
                MMA16816(o[2*nd+1], ph4[0], ph4[1], ph4[2], ph4[3], vh4[2], vh4[3]);
                MMA16816(o[2*nd+1], ph4[0], ph4[1], ph4[2], ph4[3], vl4[2], vl4[3]);
                MMA16816(o[2*nd+1], pl4[0], pl4[1], pl4[2], pl4[3], vh4[2], vh4[3]);
            }
        }
        __syncthreads();   // all warps done reading this stage before reuse
    }

    // ---- epilogue: normalize, split to bf16 hi/lo, write ctx ----
#pragma unroll
    for (int h2 = 0; h2 < 2; ++h2) {
        const int grow = q0 + wid * 16 + trow + 8 * h2;
        const float inv = 1.0f / l2[h2];
        size_t base = ((size_t)(b * S_) + grow) * QDIM + h * HD_ + tcol;
#pragma unroll
        for (int nt = 0; nt < 16; ++nt) {
            float v0 = o[nt][2*h2]     * inv;
            float v1 = o[nt][2*h2 + 1] * inv;
            __nv_bfloat16 h0 = __float2bfloat16(v0);
            __nv_bfloat16 h1 = __float2bfloat16(v1);
            __nv_bfloat16 l0 = __float2bfloat16(v0 - __bfloat162float(h0));
            __nv_bfloat16 l1 = __float2bfloat16(v1 - __bfloat162float(h1));
            __nv_bfloat162 hp; hp.x = h0; hp.y = h1;
            __nv_bfloat162 lp; lp.x = l0; lp.y = l1;
            *(__nv_bfloat162*)(ctxH + base + nt * 8) = hp;
            *(__nv_bfloat162*)(ctxL + base + nt * 8) = lp;
        }
    }
}

// ---------------- launch --------------------------------------------------
extern "C" void kernel_launch(void* const* d_in, const int* in_sizes, int n_in,
                              void* d_out, int out_size) {
    const float* hidden  = (const float*)d_in[0];
    const float* cosp    = (const float*)d_in[1];
    const float* sinp    = (const float*)d_in[2];
    // d_in[3] attention_mask: pure causal -> applied analytically
    const int*   q_qw    = (const int*)  d_in[4];
    const float* q_scale = (const float*)d_in[5];
    const int*   k_qw    = (const int*)  d_in[6];
    const float* k_scale = (const float*)d_in[7];
    const int*   v_qw    = (const int*)  d_in[8];
    const float* v_scale = (const float*)d_in[9];
    const int*   o_qw    = (const int*)  d_in[10];
    const float* o_scale = (const float*)d_in[11];
    float* out = (float*)d_out;

    void* p;
    cudaGetSymbolAddress(&p, g_hidH); __nv_bfloat16* hidH = (__nv_bfloat16*)p;
    cudaGetSymbolAddress(&p, g_hidL); __nv_bfloat16* hidL = (__nv_bfloat16*)p;
    cudaGetSymbolAddress(&p, g_Wq);   __nv_bfloat16* Wq   = (__nv_bfloat16*)p;
    cudaGetSymbolAddress(&p, g_Wk);   __nv_bfloat16* Wk   = (__nv_bfloat16*)p;
    cudaGetSymbolAddress(&p, g_Wv);   __nv_bfloat16* Wv   = (__nv_bfloat16*)p;
    cudaGetSymbolAddress(&p, g_Wo);   __nv_bfloat16* Wo   = (__nv_bfloat16*)p;
    cudaGetSymbolAddress(&p, g_ctxH); __nv_bfloat16* ctxH = (__nv_bfloat16*)p;
    cudaGetSymbolAddress(&p, g_ctxL); __nv_bfloat16* ctxL = (__nv_bfloat16*)p;
    cudaGetSymbolAddress(&p, g_sTq);  float* sTq = (float*)p;
    cudaGetSymbolAddress(&p, g_sTk);  float* sTk = (float*)p;
    cudaGetSymbolAddress(&p, g_sTv);  float* sTv = (float*)p;
    cudaGetSymbolAddress(&p, g_sTo);  float* sTo = (float*)p;
    cudaGetSymbolAddress(&p, g_Q);    float* Qb  = (float*)p;
    cudaGetSymbolAddress(&p, g_K);    float* Kb  = (float*)p;
    cudaGetSymbolAddress(&p, g_V);    float* Vb  = (float*)p;
    cudaGetSymbolAddress(&p, g_Qh);   __nv_bfloat16* Qh = (__nv_bfloat16*)p;
    cudaGetSymbolAddress(&p, g_Ql);   __nv_bfloat16* Ql = (__nv_bfloat16*)p;
    cudaGetSymbolAddress(&p, g_Kh);   __nv_bfloat16* Kh = (__nv_bfloat16*)p;
    cudaGetSymbolAddress(&p, g_Kl);   __nv_bfloat16* Kl = (__nv_bfloat16*)p;
    cudaGetSymbolAddress(&p, g_Vh);   __nv_bfloat16* Vh = (__nv_bfloat16*)p;
    cudaGetSymbolAddress(&p, g_Vl);   __nv_bfloat16* Vl = (__nv_bfloat16*)p;

    cudaFuncSetAttribute(gemm_tc,
                         cudaFuncAttributeMaxDynamicSharedMemorySize, GEMM_DSMEM);
    cudaFuncSetAttribute(attn_tc,
                         cudaFuncAttributeMaxDynamicSharedMemorySize, ATTN_SMEM_B);

    // 1) dequant weights to exact bf16 (q-8), transpose scales
    {
        int t4;
        t4 = QDIM * HID_ / 4;
        dequant_bf16_kernel<<<(t4 + 255) / 256, 256>>>(q_qw, Wq, t4);
        t4 = KVDIM * HID_ / 4;
        dequant_bf16_kernel<<<(t4 + 255) / 256, 256>>>(k_qw, Wk, t4);
        dequant_bf16_kernel<<<(t4 + 255) / 256, 256>>>(v_qw, Wv, t4);
        t4 = HID_ * QDIM / 4;
        dequant_bf16_kernel<<<(t4 + 255) / 256, 256>>>(o_qw, Wo, t4);

        int ts;
        ts = QDIM * NGRP;
        scale_T_kernel<<<(ts + 255) / 256, 256>>>(q_scale, sTq, QDIM);
        ts = KVDIM * NGRP;
        scale_T_kernel<<<(ts + 255) / 256, 256>>>(k_scale, sTk, KVDIM);
        scale_T_kernel<<<(ts + 255) / 256, 256>>>(v_scale, sTv, KVDIM);
        ts = HID_ * NGRP;
        scale_T_kernel<<<(ts + 255) / 256, 256>>>(o_scale, sTo, HID_);
    }

    // 2) split hidden states into bf16 hi/lo
    {
        int t4 = M_ * HID_ / 4;
        split_kernel<<<(t4 + 255) / 256, 256>>>(hidden, hidH, hidL, t4);
    }

    // 3) Q/K/V projections on HMMA tensor cores (fp32 out)
    gemm_tc<<<dim3(QDIM / 128,  M_ / 128), 512, GEMM_DSMEM>>>(hidH, hidL, Wq, sTq, Qb, QDIM);
    gemm_tc<<<dim3(KVDIM / 128, M_ / 128), 512, GEMM_DSMEM>>>(hidH, hidL, Wk, sTk, Kb, KVDIM);
    gemm_tc<<<dim3(KVDIM / 128, M_ / 128), 512, GEMM_DSMEM>>>(hidH, hidL, Wv, sTv, Vb, KVDIM);

    // 4) RoPE + split Q/K to bf16 hi/lo; split V
    {
        int tot = M_ * (NH_ + NKV_) * 64;
        rope_split_kernel<<<(tot + 255) / 256, 256>>>(Qb, Kb, cosp, sinp, Qh, Ql, Kh, Kl);
        int t4 = M_ * KVDIM / 4;
        split_kernel<<<(t4 + 255) / 256, 256>>>(Vb, Vh, Vl, t4);
    }

    // 5) HMMA flash attention -> ctxH/ctxL (bf16 hi/lo, split in epilogue)
    attn_tc<<<dim3(S_ / 128, NH_, B_), 256, ATTN_SMEM_B>>>(Qh, Ql, Kh, Kl, Vh, Vl, ctxH, ctxL);

    // 6) O-projection on HMMA -> d_out
    gemm_tc<<<dim3(HID_ / 128, M_ / 128), 512, GEMM_DSMEM>>>(ctxH, ctxL, Wo, sTo, out, HID_);
}

// round 10
// speedup vs baseline: 3.7899x; 1.0008x over previous
#include <cuda_runtime.h>
#include <cuda_bf16.h>
#include <cstdint>

// ---------------- problem constants ----------------
#define B_    2
#define S_    2048
#define HID_  4096
#define NH_   32
#define NKV_  8
#define HD_   128
#define G_    128
#define M_    (B_*S_)        // 4096 tokens
#define QDIM  (NH_*HD_)      // 4096
#define KVDIM (NKV_*HD_)     // 1024
#define NGRP  (HID_/G_)      // 32

// ---------------- device scratch (no allocations allowed) ----------------
__device__ __nv_bfloat16 g_hidH[M_*HID_],  g_hidL[M_*HID_];
__device__ __nv_bfloat16 g_Wq[QDIM*HID_];
__device__ __nv_bfloat16 g_Wk[KVDIM*HID_];
__device__ __nv_bfloat16 g_Wv[KVDIM*HID_];
__device__ __nv_bfloat16 g_Wo[HID_*QDIM];
__device__ __nv_bfloat16 g_ctxH[M_*QDIM],  g_ctxL[M_*QDIM];
__device__ float g_sTq[NGRP*QDIM];
__device__ float g_sTk[NGRP*KVDIM];
__device__ float g_sTv[NGRP*KVDIM];
__device__ float g_sTo[NGRP*HID_];
__device__ float g_Q [M_*QDIM];
__device__ float g_K [M_*KVDIM];
__device__ float g_V [M_*KVDIM];
__device__ __nv_bfloat16 g_Qh[M_*QDIM],  g_Ql[M_*QDIM];
__device__ __nv_bfloat16 g_Kh[M_*KVDIM], g_Kl[M_*KVDIM];
__device__ __nv_bfloat16 g_Vh[M_*KVDIM], g_Vl[M_*KVDIM];

// ================= low-level helpers (sm_80-compatible PTX only) =========
__device__ __forceinline__ uint32_t smem_u32(const void* p) {
    uint32_t a;
    asm("{ .reg .u64 t; cvta.to.shared.u64 t, %1; cvt.u32.u64 %0, t; }"
        : "=r"(a) : "l"(p));
    return a;
}

#define CPA16(dst, src) \
    asm volatile("cp.async.cg.shared.global [%0], [%1], 16;" \
        :: "r"(dst), "l"(src) : "memory")

#define LDSM4(R0, R1, R2, R3, addr) \
    asm volatile("ldmatrix.sync.aligned.m8n8.x4.shared.b16 {%0,%1,%2,%3}, [%4];" \
        : "=r"(R0), "=r"(R1), "=r"(R2), "=r"(R3) : "r"(addr))

#define LDSM4T(R0, R1, R2, R3, addr) \
    asm volatile("ldmatrix.sync.aligned.m8n8.x4.trans.shared.b16 {%0,%1,%2,%3}, [%4];" \
        : "=r"(R0), "=r"(R1), "=r"(R2), "=r"(R3) : "r"(addr))

#define MMA16816(d, a0, a1, a2, a3, b0, b1) \
    asm volatile("mma.sync.aligned.m16n8k16.row.col.f32.bf16.bf16.f32 " \
        "{%0,%1,%2,%3}, {%4,%5,%6,%7}, {%8,%9}, {%0,%1,%2,%3};" \
        : "+f"((d)[0]), "+f"((d)[1]), "+f"((d)[2]), "+f"((d)[3]) \
        : "r"(a0), "r"(a1), "r"(a2), "r"(a3), "r"(b0), "r"(b1))

__device__ __forceinline__ float fast_exp2(float x) {
    float r;
    asm("ex2.approx.ftz.f32 %0, %1;" : "=f"(r) : "f"(x));
    return r;
}

// ---------------- dequant: (qw - 8) -> exact bf16 ------------------------
__global__ void dequant_bf16_kernel(const int* __restrict__ qw,
                                    __nv_bfloat16* __restrict__ w, int total4) {
    int idx = blockIdx.x * blockDim.x + threadIdx.x;
    if (idx >= total4) return;
    int4 q = ((const int4*)qw)[idx];
    ushort4 hv;
    hv.x = __bfloat16_as_ushort(__float2bfloat16((float)(q.x - 8)));
    hv.y = __bfloat16_as_ushort(__float2bfloat16((float)(q.y - 8)));
    hv.z = __bfloat16_as_ushort(__float2bfloat16((float)(q.z - 8)));
    hv.w = __bfloat16_as_ushort(__float2bfloat16((float)(q.w - 8)));
    ((ushort4*)w)[idx] = hv;
}

// ---------------- scale transpose: sT[g][o] = s[o][g] ---------------------
__global__ void scale_T_kernel(const float* __restrict__ s,
                               float* __restrict__ sT, int outdim) {
    int idx = blockIdx.x * blockDim.x + threadIdx.x;
    if (idx >= outdim * NGRP) return;
    int g = idx / outdim;
    int o = idx - g * outdim;
    sT[idx] = s[o * NGRP + g];
}

// ---------------- f32 -> bf16 hi/lo split ---------------------------------
__global__ void split_kernel(const float* __restrict__ x,
                             __nv_bfloat16* __restrict__ xh,
                             __nv_bfloat16* __restrict__ xl, int total4) {
    int idx = blockIdx.x * blockDim.x + threadIdx.x;
    if (idx >= total4) return;
    float4 v = ((const float4*)x)[idx];
    float w[4] = {v.x, v.y, v.z, v.w};
    ushort4 hv, lv;
    unsigned short* hp = &hv.x; unsigned short* lp = &lv.x;
#pragma unroll
    for (int j = 0; j < 4; ++j) {
        __nv_bfloat16 h = __float2bfloat16(w[j]);
        __nv_bfloat16 l = __float2bfloat16(w[j] - __bfloat162float(h));
        hp[j] = __bfloat16_as_ushort(h);
        lp[j] = __bfloat16_as_ushort(l);
    }
    ((ushort4*)xh)[idx] = hv;
    ((ushort4*)xl)[idx] = lv;
}

// ---------------- RoPE + hi/lo split for Q and K ---------------------------
__global__ void rope_split_kernel(const float* __restrict__ Q,
                                  const float* __restrict__ K,
                                  const float* __restrict__ cosp,
                                  const float* __restrict__ sinp,
                                  __nv_bfloat16* __restrict__ Qh,
                                  __nv_bfloat16* __restrict__ Ql,
                                  __nv_bfloat16* __restrict__ Kh,
                                  __nv_bfloat16* __restrict__ Kl) {
    int t = blockIdx.x * blockDim.x + threadIdx.x;
    const int TOT = M_ * (NH_ + NKV_) * 64;
    if (t >= TOT) return;
    int d = t & 63;
    int r = t >> 6;
    int h = r % (NH_ + NKV_);
    int m = r / (NH_ + NKV_);
    float c1 = cosp[m * HD_ + d],      s1 = sinp[m * HD_ + d];
    float c2 = cosp[m * HD_ + d + 64], s2 = sinp[m * HD_ + d + 64];
    const float* base;
    __nv_bfloat16 *oh, *ol;
    size_t off;
    if (h < NH_) {
        off = (size_t)m * QDIM + h * HD_;
        base = Q + off; oh = Qh; ol = Ql;
    } else {
        off = (size_t)m * KVDIM + (h - NH_) * HD_;
        base = K + off; oh = Kh; ol = Kl;
    }
    float x1 = base[d], x2 = base[d + 64];
    float y1 = x1 * c1 - x2 * s1;
    float y2 = x2 * c2 + x1 * s2;
    __nv_bfloat16 h1 = __float2bfloat16(y1);
    __nv_bfloat16 h2 = __float2bfloat16(y2);
    oh[off + d]      = h1;
    oh[off + d + 64] = h2;
    ol[off + d]      = __float2bfloat16(y1 - __bfloat162float(h1));
    ol[off + d + 64] = __float2bfloat16(y2 - __bfloat162float(h2));
}

// ---------------- HMMA GEMM with grouped scales (3-stage pipeline) --------
#define BK      64
#define LDA     72
#define MAT_B   (128*LDA*2)            // 18432 B per matrix per stage
#define STAGE_B (3*MAT_B)              // Ah, Al, W
#define NCHUNK  (HID_/BK)              // 64
#define GEMM_DSMEM (3*STAGE_B)         // 165888 B

__global__ __launch_bounds__(512, 1)
void gemm_tc(const __nv_bfloat16* __restrict__ Ah,
             const __nv_bfloat16* __restrict__ Al,
             const __nv_bfloat16* __restrict__ Bw,
             const float* __restrict__ sT,
             float* __restrict__ C, int N) {
    extern __shared__ char dsm[];
    const uint32_t sb = smem_u32(dsm);

    const int tid  = threadIdx.x;
    const int wid  = tid >> 5;
    const int lane = tid & 31;
    const int m0 = blockIdx.y << 7, n0 = blockIdx.x << 7;
    const int wm0 = (wid & 3) << 5;
    const int wn0 = (wid >> 2) << 5;

    const char* pAh = (const char*)(Ah + (size_t)m0 * HID_);
    const char* pAl = (const char*)(Al + (size_t)m0 * HID_);
    const char* pBw = (const char*)(Bw + (size_t)n0 * HID_);
    const size_t ROWB = HID_ * 2;

    auto load_chunk = [&](int c, int st) {
        const uint32_t base = sb + (uint32_t)st * STAGE_B;
        const size_t koff = (size_t)c * (BK * 2);
#pragma unroll
        for (int i = 0; i < 6; ++i) {
            int u   = i * 512 + tid;
            int mat = u >> 10;
            int rem = u & 1023;
            int row = rem >> 3;
            int cu  = rem & 7;
            const char* p = (mat == 0) ? pAh : (mat == 1) ? pAl : pBw;
            uint32_t dst = base + (uint32_t)mat * MAT_B + row * (LDA * 2) + cu * 16;
            CPA16(dst, p + (size_t)row * ROWB + koff + cu * 16);
        }
        asm volatile("cp.async.commit_group;" ::: "memory");
    };

    float acc[2][4][4], part[2][4][4];
#pragma unroll
    for (int mt = 0; mt < 2; ++mt)
#pragma unroll
        for (int nt = 0; nt < 4; ++nt)
#pragma unroll
            for (int r = 0; r < 4; ++r) { acc[mt][nt][r] = 0.f; part[mt][nt][r] = 0.f; }

    const float* sPtr = sT + (n0 + wn0 + ((lane & 3) << 1));

    const int lrow = lane & 15;
    const int lcolh = (lane >> 4) << 3;

    load_chunk(0, 0);
    load_chunk(1, 1);

    int st = 0;
    for (int it = 0; it < NCHUNK; ++it) {
        if (it + 1 < NCHUNK) {
            asm volatile("cp.async.wait_group 1;" ::: "memory");
        } else {
            asm volatile("cp.async.wait_group 0;" ::: "memory");
        }
        __syncthreads();

        int s2 = st + 2; if (s2 >= 3) s2 -= 3;
        if (it + 2 < NCHUNK) load_chunk(it + 2, s2);

        const uint32_t sAh = sb + (uint32_t)st * STAGE_B;
        const uint32_t sAl = sAh + MAT_B;
        const uint32_t sBB = sAh + 2 * MAT_B;

#pragma unroll
        for (int ks = 0; ks < 4; ++ks) {
            const uint32_t col = (ks << 4) + lcolh;
            uint32_t ah[2][4], al[2][4];
#pragma unroll
            for (int mt = 0; mt < 2; ++mt) {
                uint32_t ra = (uint32_t)((wm0 + (mt << 4) + lrow) * LDA + col) * 2;
                LDSM4(ah[mt][0], ah[mt][1], ah[mt][2], ah[mt][3], sAh + ra);
                LDSM4(al[mt][0], al[mt][1], al[mt][2], al[mt][3], sAl + ra);
            }
            uint32_t bb[2][4];
#pragma unroll
            for (int p = 0; p < 2; ++p) {
                uint32_t rb = (uint32_t)((wn0 + (p << 4) + lrow) * LDA + col) * 2;
                LDSM4(bb[p][0], bb[p][1], bb[p][2], bb[p][3], sBB + rb);
            }
#pragma unroll
            for (int mt = 0; mt < 2; ++mt)
#pragma unroll
                for (int nt = 0; nt < 4; ++nt) {
                    const int p = nt >> 1, h = nt & 1;
                    MMA16816(part[mt][nt],
                             ah[mt][0], ah[mt][1], ah[mt][2], ah[mt][3],
                             bb[p][h], bb[p][h + 2]);
                    MMA16816(part[mt][nt],
                             al[mt][0], al[mt][1], al[mt][2], al[mt][3],
                             bb[p][h], bb[p][h + 2]);
                }
        }

        if (it & 1) {
#pragma unroll
            for (int nt = 0; nt < 4; ++nt) {
                float2 sv = *(const float2*)(sPtr + nt * 8);
#pragma unroll
                for (int mt = 0; mt < 2; ++mt) {
                    acc[mt][nt][0] += sv.x * part[mt][nt][0];
                    acc[mt][nt][1] += sv.y * part[mt][nt][1];
                    acc[mt][nt][2] += sv.x * part[mt][nt][2];
                    acc[mt][nt][3] += sv.y * part[mt][nt][3];
                    part[mt][nt][0] = 0.f; part[mt][nt][1] = 0.f;
                    part[mt][nt][2] = 0.f; part[mt][nt][3] = 0.f;
                }
            }
            sPtr += N;
        }

        ++st; if (st == 3) st = 0;
    }

    const int colg = n0 + wn0 + ((lane & 3) << 1);
#pragma unroll
    for (int mt = 0; mt < 2; ++mt) {
        const int r0 = m0 + wm0 + (mt << 4) + (lane >> 2);
#pragma unroll
        for (int nt = 0; nt < 4; ++nt) {
            float2 v0 = {acc[mt][nt][0], acc[mt][nt][1]};
            float2 v1 = {acc[mt][nt][2], acc[mt][nt][3]};
            *(float2*)(C + (size_t)r0 * N + colg + nt * 8)       = v0;
            *(float2*)(C + (size_t)(r0 + 8) * N + colg + nt * 8) = v1;
        }
    }
}

// ---------------- HMMA flash attention (causal) ----------------------------
// CTA: 128 q-rows x one head x batch; 8 warps (warp = 16 q-rows).
// K/V tiles 64 x 128 hi/lo, double-buffered cp.async. Q frags in registers.
// 3-term QK (QhKh+QhKl+QlKh) and 3-term PV (PhVh+PhVl+PlVh).
#define LDK 136
#define LDP 72
#define KMAT_B (64*LDK*2)              // 17408
#define KV_STAGE_B (4*KMAT_B)          // 69632
#define ATTN_PH_OFF (2*KV_STAGE_B)     // 139264
#define ATTN_PL_OFF (ATTN_PH_OFF + 128*LDP*2)
#define ATTN_SMEM_B (ATTN_PL_OFF + 128*LDP*2)   // 176128

__global__ __launch_bounds__(256, 1)
void attn_tc(const __nv_bfloat16* __restrict__ Qhg, const __nv_bfloat16* __restrict__ Qlg,
             const __nv_bfloat16* __restrict__ Khg, const __nv_bfloat16* __restrict__ Klg,
             const __nv_bfloat16* __restrict__ Vhg, const __nv_bfloat16* __restrict__ Vlg,
             __nv_bfloat16* __restrict__ ctxH, __nv_bfloat16* __restrict__ ctxL) {
    extern __shared__ char smc[];
    const uint32_t sb = smem_u32(smc);

    const int qi = blockIdx.x, h = blockIdx.y, b = blockIdx.z;
    const int kvh = h >> 2;
    const int tid = threadIdx.x, wid = tid >> 5, lane = tid & 31;
    const int q0 = qi << 7;
    const int nk = 2 * qi + 2;

    const int lrow  = lane & 15;
    const int lcol8 = (lane >> 4) << 3;
    const int trow  = lane >> 2;          // 0..7
    const int tcol  = (lane & 3) << 1;    // 0,2,4,6

    // SCALING/sqrt(d) folded with log2(e): softmax computed in base 2
    const float SC2 = 0.08838834764831843f * 1.4426950408889634f;

    // ---- stage Q tile, build register fragments (hi then lo) ----
    uint32_t qhf[8][4], qlf[8][4];
    {
        const __nv_bfloat16* srcH = Qhg + ((size_t)(b * S_ + q0)) * QDIM + h * HD_;
        const __nv_bfloat16* srcL = Qlg + ((size_t)(b * S_ + q0)) * QDIM + h * HD_;
#pragma unroll
        for (int pass = 0; pass < 2; ++pass) {
            const char* src = (const char*)(pass ? srcL : srcH);
#pragma unroll
            for (int i = 0; i < 8; ++i) {
                int u = tid + (i << 8);
                int row = u >> 4, cu = u & 15;
                *(uint4*)(smc + row * (LDK * 2) + cu * 16) =
                    *(const uint4*)(src + (size_t)row * (QDIM * 2) + cu * 16);
            }
            __syncthreads();
#pragma unroll
            for (int ks = 0; ks < 8; ++ks) {
                uint32_t a = sb + (uint32_t)((wid * 16 + lrow) * LDK + ks * 16 + lcol8) * 2;
                if (pass == 0) LDSM4(qhf[ks][0], qhf[ks][1], qhf[ks][2], qhf[ks][3], a);
                else           LDSM4(qlf[ks][0], qlf[ks][1], qlf[ks][2], qlf[ks][3], a);
            }
            __syncthreads();
        }
    }

    float m2[2] = {-1e30f, -1e30f}, l2[2] = {0.f, 0.f};
    float o[16][4];
#pragma unroll
    for (int i = 0; i < 16; ++i)
#pragma unroll
        for (int j = 0; j < 4; ++j) o[i][j] = 0.f;

    const char* kh_g = (const char*)(Khg + ((size_t)(b * S_)) * KVDIM + kvh * HD_);
    const char* kl_g = (const char*)(Klg + ((size_t)(b * S_)) * KVDIM + kvh * HD_);
    const char* vh_g = (const char*)(Vhg + ((size_t)(b * S_)) * KVDIM + kvh * HD_);
    const char* vl_g = (const char*)(Vlg + ((size_t)(b * S_)) * KVDIM + kvh * HD_);
    const size_t KROWB = KVDIM * 2;

    auto prefetch = [&](int kt, int stg) {
        const uint32_t base = sb + (uint32_t)stg * KV_STAGE_B;
        const size_t g0 = (size_t)(kt << 6) * KROWB;
#pragma unroll
        for (int i = 0; i < 16; ++i) {
            int u = tid + (i << 8);
            int mat = u >> 10;
            int rem = u & 1023, row = rem >> 4, cu = rem & 15;
            const char* g = (mat == 0) ? kh_g : (mat == 1) ? kl_g
                          : (mat == 2) ? vh_g : vl_g;
            CPA16(base + (uint32_t)mat * KMAT_B + row * (LDK * 2) + cu * 16,
                  g + g0 + (size_t)row * KROWB + cu * 16);
        }
        asm volatile("cp.async.commit_group;" ::: "memory");
    };

    prefetch(0, 0);

    for (int kt = 0; kt < nk; ++kt) {
        const int stg = kt & 1;
        const int k0 = kt << 6;
        if (kt + 1 < nk) {
            prefetch(kt + 1, stg ^ 1);
            asm volatile("cp.async.wait_group 1;" ::: "memory");
        } else {
            asm volatile("cp.async.wait_group 0;" ::: "memory");
        }
        __syncthreads();

        const uint32_t kv = sb + (uint32_t)stg * KV_STAGE_B;

        // ---- scores: S = Qh Kh^T + Qh Kl^T + Ql Kh^T ----
        float sc[8][4];
#pragma unroll
        for (int i = 0; i < 8; ++i)
#pragma unroll
            for (int j = 0; j < 4; ++j) sc[i][j] = 0.f;

#pragma unroll
        for (int ks = 0; ks < 8; ++ks) {
#pragma unroll
            for (int p = 0; p < 4; ++p) {
                uint32_t ka = kv + (uint32_t)((p * 16 + lrow) * LDK + ks * 16 + lcol8) * 2;
                uint32_t kh4[4], kl4[4];
                LDSM4(kh4[0], kh4[1], kh4[2], kh4[3], ka);
                LDSM4(kl4[0], kl4[1], kl4[2], kl4[3], ka + KMAT_B);
                MMA16816(sc[2*p], qhf[ks][0], qhf[ks][1], qhf[ks][2], qhf[ks][3], kh4[0], kh4[2]);
                MMA16816(sc[2*p], qhf[ks][0], qhf[ks][1], qhf[ks][2], qhf[ks][3], kl4[0], kl4[2]);
                MMA16816(sc[2*p], qlf[ks][0], qlf[ks][1], qlf[ks][2], qlf[ks][3], kh4[0], kh4[2]);
                MMA16816(sc[2*p+1], qhf[ks][0], qhf[ks][1], qhf[ks][2], qhf[ks][3], kh4[1], kh4[3]);
                MMA16816(sc[2*p+1], qhf[ks][0], qhf[ks][1], qhf[ks][2], qhf[ks][3], kl4[1], kl4[3]);
                MMA16816(sc[2*p+1], qlf[ks][0], qlf[ks][1], qlf[ks][2], qlf[ks][3], kh4[1], kh4[3]);
            }
        }

        // ---- scale + causal mask (only needed on the last two k-tiles) ----
        const bool needMask = (kt >= nk - 2);
#pragma unroll
        for (int h2 = 0; h2 < 2; ++h2) {
            const int grow = q0 + wid * 16 + trow + 8 * h2;
#pragma unroll
            for (int nt = 0; nt < 8; ++nt)
#pragma unroll
                for (int j = 0; j < 2; ++j) {
                    float x = sc[nt][2*h2 + j] * SC2;
                    if (needMask && (k0 + nt * 8 + tcol + j) > grow) x = -1e30f;
                    sc[nt][2*h2 + j] = x;
                }
        }

        // ---- online softmax (base-2), P -> hi/lo bf16 into smem ----
#pragma unroll
        for (int h2 = 0; h2 < 2; ++h2) {
            float mx = -1e30f;
#pragma unroll
            for (int nt = 0; nt < 8; ++nt) {
                mx = fmaxf(mx, sc[nt][2*h2]);
                mx = fmaxf(mx, sc[nt][2*h2 + 1]);
            }
            mx = fmaxf(mx, __shfl_xor_sync(0xffffffffu, mx, 1));
            mx = fmaxf(mx, __shfl_xor_sync(0xffffffffu, mx, 2));
            float mnew = fmaxf(m2[h2], mx);
            float corr = fast_exp2(m2[h2] - mnew);
            m2[h2] = mnew;

            float rs = 0.f;
            const int prow = wid * 16 + trow + 8 * h2;
#pragma unroll
            for (int nt = 0; nt < 8; ++nt) {
                float p0 = fast_exp2(sc[nt][2*h2]     - mnew);
                float p1 = fast_exp2(sc[nt][2*h2 + 1] - mnew);
                rs += p0 + p1;
                __nv_bfloat16 h0 = __float2bfloat16(p0);
                __nv_bfloat16 h1 = __float2bfloat16(p1);
                __nv_bfloat16 l0 = __float2bfloat16(p0 - __bfloat162float(h0));
                __nv_bfloat16 l1 = __float2bfloat16(p1 - __bfloat162float(h1));
                __nv_bfloat162 hp; hp.x = h0; hp.y = h1;
                __nv_bfloat162 lp; lp.x = l0; lp.y = l1;
                *(__nv_bfloat162*)(smc + ATTN_PH_OFF + (prow * LDP + nt * 8 + tcol) * 2) = hp;
                *(__nv_bfloat162*)(smc + ATTN_PL_OFF + (prow * LDP + nt * 8 + tcol) * 2) = lp;
            }
            rs += __shfl_xor_sync(0xffffffffu, rs, 1);
            rs += __shfl_xor_sync(0xffffffffu, rs, 2);
            l2[h2] = l2[h2] * corr + rs;
#pragma unroll
            for (int nt = 0; nt < 16; ++nt) {
                o[nt][2*h2]     *= corr;
                o[nt][2*h2 + 1] *= corr;
            }
        }
        __syncwarp();

        // ---- O += Ph Vh + Ph Vl + Pl Vh ----
#pragma unroll
        for (int ks2 = 0; ks2 < 4; ++ks2) {
            uint32_t pa = sb + ATTN_PH_OFF +
                (uint32_t)((wid * 16 + lrow) * LDP + ks2 * 16 + lcol8) * 2;
            uint32_t ph4[4], pl4[4];
            LDSM4(ph4[0], ph4[1], ph4[2], ph4[3], pa);
            LDSM4(pl4[0], pl4[1], pl4[2], pl4[3], pa + (ATTN_PL_OFF - ATTN_PH_OFF));
#pragma unroll
            for (int nd = 0; nd < 8; ++nd) {
                uint32_t va = kv + 2 * KMAT_B +
                    (uint32_t)((ks2 * 16 + lrow) * LDK + nd * 16 + lcol8) * 2;
                uint32_t vh4[4], vl4[4];
                LDSM4T(vh4[0], vh4[1], vh4[2], vh4[3], va);
                LDSM4T(vl4[0], vl4[1], vl4[2], vl4[3], va + KMAT_B);
                MMA16816(o[2*nd], ph4[0], ph4[1], ph4[2], ph4[3], vh4[0], vh4[1]);
                MMA16816(o[2*nd], ph4[0], ph4[1], ph4[2], ph4[3], vl4[0], vl4[1]);
                MMA16816(o[2*nd], pl4[0], pl4[1], pl4[2], pl4[3], vh4[0], vh4[1]);
                MMA16816(o[2*nd+1], ph4[0], ph4[1], ph4[2], ph4[3], vh4[2], vh4[3]);
                MMA16816(o[2*nd+1], ph4[0], ph4[1], ph4[2], ph4[3], vl4[2], vl4[3]);
                MMA16816(o[2*nd+1], pl4[0], pl4[1], pl4[2], pl4[3], vh4[2], vh4[3]);
            }
        }
        __syncthreads();   // all warps done reading this stage before reuse
    }

    // ---- epilogue: normalize, split to bf16 hi/lo, write ctx ----
#pragma unroll
    for (int h2 = 0; h2 < 2; ++h2) {
        const int grow = q0 + wid * 16 + trow + 8 * h2;
        const float inv = 1.0f / l2[h2];
        size_t base = ((size_t)(b * S_) + grow) * QDIM + h * HD_ + tcol;
#pragma unroll
        for (int nt = 0; nt < 16; ++nt) {
            float v0 = o[nt][2*h2]     * inv;
            float v1 = o[nt][2*h2 + 1] * inv;
            __nv_bfloat16 h0 = __float2bfloat16(v0);
            __nv_bfloat16 h1 = __float2bfloat16(v1);
            __nv_bfloat16 l0 = __float2bfloat16(v0 - __bfloat162float(h0));
            __nv_bfloat16 l1 = __float2bfloat16(v1 - __bfloat162float(h1));
            __nv_bfloat162 hp; hp.x = h0; hp.y = h1;
            __nv_bfloat162 lp; lp.x = l0; lp.y = l1;
            *(__nv_bfloat162*)(ctxH + base + nt * 8) = hp;
            *(__nv_bfloat162*)(ctxL + base + nt * 8) = lp;
        }
    }
}

// ---------------- launch --------------------------------------------------
extern "C" void kernel_launch(void* const* d_in, const int* in_sizes, int n_in,
                              void* d_out, int out_size) {
    const float* hidden  = (const float*)d_in[0];
    const float* cosp    = (const float*)d_in[1];
    const float* sinp    = (const float*)d_in[2];
    // d_in[3] attention_mask: pure causal -> applied analytically
    const int*   q_qw    = (const int*)  d_in[4];
    const float* q_scale = (const float*)d_in[5];
    const int*   k_qw    = (const int*)  d_in[6];
    const float* k_scale = (const float*)d_in[7];
    const int*   v_qw    = (const int*)  d_in[8];
    const float* v_scale = (const float*)d_in[9];
    const int*   o_qw    = (const int*)  d_in[10];
    const float* o_scale = (const float*)d_in[11];
    float* out = (float*)d_out;

    void* p;
    cudaGetSymbolAddress(&p, g_hidH); __nv_bfloat16* hidH = (__nv_bfloat16*)p;
    cudaGetSymbolAddress(&p, g_hidL); __nv_bfloat16* hidL = (__nv_bfloat16*)p;
    cudaGetSymbolAddress(&p, g_Wq);   __nv_bfloat16* Wq   = (__nv_bfloat16*)p;
    cudaGetSymbolAddress(&p, g_Wk);   __nv_bfloat16* Wk   = (__nv_bfloat16*)p;
    cudaGetSymbolAddress(&p, g_Wv);   __nv_bfloat16* Wv   = (__nv_bfloat16*)p;
    cudaGetSymbolAddress(&p, g_Wo);   __nv_bfloat16* Wo   = (__nv_bfloat16*)p;
    cudaGetSymbolAddress(&p, g_ctxH); __nv_bfloat16* ctxH = (__nv_bfloat16*)p;
    cudaGetSymbolAddress(&p, g_ctxL); __nv_bfloat16* ctxL = (__nv_bfloat16*)p;
    cudaGetSymbolAddress(&p, g_sTq);  float* sTq = (float*)p;
    cudaGetSymbolAddress(&p, g_sTk);  float* sTk = (float*)p;
    cudaGetSymbolAddress(&p, g_sTv);  float* sTv = (float*)p;
    cudaGetSymbolAddress(&p, g_sTo);  float* sTo = (float*)p;
    cudaGetSymbolAddress(&p, g_Q);    float* Qb  = (float*)p;
    cudaGetSymbolAddress(&p, g_K);    float* Kb  = (float*)p;
    cudaGetSymbolAddress(&p, g_V);    float* Vb  = (float*)p;
    cudaGetSymbolAddress(&p, g_Qh);   __nv_bfloat16* Qh = (__nv_bfloat16*)p;
    cudaGetSymbolAddress(&p, g_Ql);   __nv_bfloat16* Ql = (__nv_bfloat16*)p;
    cudaGetSymbolAddress(&p, g_Kh);   __nv_bfloat16* Kh = (__nv_bfloat16*)p;
    cudaGetSymbolAddress(&p, g_Kl);   __nv_bfloat16* Kl = (__nv_bfloat16*)p;
    cudaGetSymbolAddress(&p, g_Vh);   __nv_bfloat16* Vh = (__nv_bfloat16*)p;
    cudaGetSymbolAddress(&p, g_Vl);   __nv_bfloat16* Vl = (__nv_bfloat16*)p;

    cudaFuncSetAttribute(gemm_tc,
                         cudaFuncAttributeMaxDynamicSharedMemorySize, GEMM_DSMEM);
    cudaFuncSetAttribute(attn_tc,
                         cudaFuncAttributeMaxDynamicSharedMemorySize, ATTN_SMEM_B);

    // 1) dequant weights to exact bf16 (q-8), transpose scales
    {
        int t4;
        t4 = QDIM * HID_ / 4;
        dequant_bf16_kernel<<<(t4 + 255) / 256, 256>>>(q_qw, Wq, t4);
        t4 = KVDIM * HID_ / 4;
        dequant_bf16_kernel<<<(t4 + 255) / 256, 256>>>(k_qw, Wk, t4);
        dequant_bf16_kernel<<<(t4 + 255) / 256, 256>>>(v_qw, Wv, t4);
        t4 = HID_ * QDIM / 4;
        dequant_bf16_kernel<<<(t4 + 255) / 256, 256>>>(o_qw, Wo, t4);

        int ts;
        ts = QDIM * NGRP;
        scale_T_kernel<<<(ts + 255) / 256, 256>>>(q_scale, sTq, QDIM);
        ts = KVDIM * NGRP;
        scale_T_kernel<<<(ts + 255) / 256, 256>>>(k_scale, sTk, KVDIM);
        scale_T_kernel<<<(ts + 255) / 256, 256>>>(v_scale, sTv, KVDIM);
        ts = HID_ * NGRP;
        scale_T_kernel<<<(ts + 255) / 256, 256>>>(o_scale, sTo, HID_);
    }

    // 2) split hidden states into bf16 hi/lo
    {
        int t4 = M_ * HID_ / 4;
        split_kernel<<<(t4 + 255) / 256, 256>>>(hidden, hidH, hidL, t4);
    }

    // 3) Q/K/V projections on HMMA tensor cores (fp32 out)
    gemm_tc<<<dim3(QDIM / 128,  M_ / 128), 512, GEMM_DSMEM>>>(hidH, hidL, Wq, sTq, Qb, QDIM);
    gemm_tc<<<dim3(KVDIM / 128, M_ / 128), 512, GEMM_DSMEM>>>(hidH, hidL, Wk, sTk, Kb, KVDIM);
    gemm_tc<<<dim3(KVDIM / 128, M_ / 128), 512, GEMM_DSMEM>>>(hidH, hidL, Wv, sTv, Vb, KVDIM);

    // 4) RoPE + split Q/K to bf16 hi/lo; split V
    {
        int tot = M_ * (NH_ + NKV_) * 64;
        rope_split_kernel<<<(tot + 255) / 256, 256>>>(Qb, Kb, cosp, sinp, Qh, Ql, Kh, Kl);
        int t4 = M_ * KVDIM / 4;
        split_kernel<<<(t4 + 255) / 256, 256>>>(Vb, Vh, Vl, t4);
    }

    // 5) HMMA flash attention -> ctxH/ctxL (bf16 hi/lo, split in epilogue)
    attn_tc<<<dim3(S_ / 128, NH_, B_), 256, ATTN_SMEM_B>>>(Qh, Ql, Kh, Kl, Vh, Vl, ctxH, ctxL);

    // 6) O-projection on HMMA -> d_out
    gemm_tc<<<dim3(HID_ / 128, M_ / 128), 512, GEMM_DSMEM>>>(ctxH, ctxL, Wo, sTo, out, HID_);
}